// round 8
// baseline (speedup 1.0000x reference)
#include <cuda_runtime.h>
#include <cstdint>

// ---------------------------------------------------------------------------
// SpectralConv2d (FNO) without FFT — tf32 mma.sync pipeline with fusion:
//   f12 : per-bc fused  F1 (t1 = Bt . x^T, in smem) + F2 (T2 = A2 . t1^T)
//   trz : z-branch mode transpose T2 -> T2z
//   mix : fp32 FFMA channel mix, plane-major S2T output (tf32-rounded)
//   i12 : per-bco fused I1 (Y = A3 . S^T, in smem) + I2 (out = Y . Cm^T)
// Intermediates t1 and Y never touch HBM.
// ---------------------------------------------------------------------------

namespace {
constexpr int ROWS_   = 131072;
constexpr int OUTOFF_ = 33554432;
constexpr int F12_SMEM = (128 * 258 + 2 * 128 * 20 + 2 * 128 * 20) * 4;  // 173056
constexpr int I12_SMEM = (128 * 40 + 256 * 68 + 128 * 34 + 2 * 128 * 20) * 4;  // 128000
}

// ------------------------- static device scratch ---------------------------
__device__ __align__(16) float g_Bt  [128 * 256];
__device__ __align__(16) float g_A2  [128 * 512];
__device__ __align__(16) float g_A3  [512 * 128];
__device__ __align__(16) float g_CmT2[256 * 64];
__device__ __align__(16) float g_T2  [128 * 32768];      // 16MB
__device__ __align__(16) float g_T2z [128 * 16384];      // 8MB
__device__ __align__(16) float g_S2T [2 * 128 * 16384];  // 16MB (plane-major)

// ------------------------------ helpers ------------------------------------
__device__ __forceinline__ float to_tf32(float x) {
    float r; asm("cvt.rna.tf32.f32 %0, %1;" : "=f"(r) : "f"(x)); return r;
}
#define CP_ASYNC16(dst_u32, src_ptr) \
    asm volatile("cp.async.cg.shared.global [%0], [%1], 16;" :: "r"(dst_u32), "l"(src_ptr))
#define CP_COMMIT() asm volatile("cp.async.commit_group;")
#define CP_WAIT(n)  asm volatile("cp.async.wait_group %0;" :: "n"(n))
#define SADDR(p) ((uint32_t)__cvta_generic_to_shared(p))

#define MMA_TF32(d0,d1,d2,d3, a0,a1,a2,a3, b0,b1)                                   \
    asm volatile("mma.sync.aligned.m16n8k8.row.col.f32.tf32.tf32.f32 "              \
        "{%0,%1,%2,%3}, {%4,%5,%6,%7}, {%8,%9}, {%0,%1,%2,%3};"                     \
        : "+f"(d0), "+f"(d1), "+f"(d2), "+f"(d3)                                    \
        : "r"(a0), "r"(a1), "r"(a2), "r"(a3), "r"(b0), "r"(b1))

// ------------------------------ table init --------------------------------
__global__ void init_tables_k() {
    int t = blockIdx.x * blockDim.x + threadIdx.x;
    if (t >= 64 * 256) return;
    int m = t >> 8, n = t & 255;
    int mf = (m < 32) ? m : m + 192;
    int k = (mf * n) & 255;
    float s, c;
    sincospif((float)k * (1.0f / 128.0f), &s, &c);
    float tc = to_tf32(c), ts = to_tf32(s), tns = to_tf32(-s);

    g_Bt[(2 * m) * 256 + n]     = tc;
    g_Bt[(2 * m + 1) * 256 + n] = tns;
    g_A2[(2 * m) * 512 + n]           = tc;
    g_A2[(2 * m) * 512 + 256 + n]     = ts;
    g_A2[(2 * m + 1) * 512 + n]       = tns;
    g_A2[(2 * m + 1) * 512 + 256 + n] = tc;
    g_A3[(2 * n) * 128 + m]          = tc;
    g_A3[(2 * n) * 128 + 64 + m]     = tns;
    g_A3[(2 * n + 1) * 128 + m]      = ts;
    g_A3[(2 * n + 1) * 128 + 64 + m] = tc;

    int k2 = m & 31;
    int kk = (k2 * n) & 255;
    float s2, c2;
    sincospif((float)kk * (1.0f / 128.0f), &s2, &c2);
    const float sc = 1.0f / 65536.0f;
    float v;
    if (m < 32) v = (k2 == 0) ? sc : 2.0f * sc * c2;
    else        v = (k2 == 0) ? 0.0f : -2.0f * sc * s2;
    g_CmT2[n * 64 + m] = to_tf32(v);
}

// ----------------------- fused F1+F2 (per bc) ------------------------------
__global__ __launch_bounds__(256)
void f12_k(const float* __restrict__ x) {
    extern __shared__ float sm[];
    float* t1s = sm;                    // [128][258]
    float* Asm = sm + 128 * 258;        // [2][128][20]
    float* Bsm = Asm + 2 * 128 * 20;    // [2][128][20]
    int t = threadIdx.x;
    int warp = t >> 5, lane = t & 31, gid = lane >> 2, tig = lane & 3;
    int bc = blockIdx.x;
    int lr = t >> 2, lc4 = (t & 3) * 4;
    const float* xbc = x + (size_t)bc * 65536;

    // ---------------- F1: t1[128 qe][256 h], two N-passes of 128 -----------
    {
        int wm = warp & 1, wn = warp >> 1;
        for (int pass = 0; pass < 2; pass++) {
            float acc[4][4][4];
#pragma unroll
            for (int mi = 0; mi < 4; mi++)
#pragma unroll
                for (int ni = 0; ni < 4; ni++)
#pragma unroll
                    for (int r = 0; r < 4; r++) acc[mi][ni][r] = 0.0f;

#pragma unroll
            for (int i = 0; i < 2; i++) {
                int r = i * 64 + lr;
                CP_ASYNC16(SADDR(&Asm[r * 20 + lc4]), &g_Bt[r * 256 + lc4]);
                CP_ASYNC16(SADDR(&Bsm[r * 20 + lc4]),
                           &xbc[(size_t)(pass * 128 + r) * 256 + lc4]);
            }
            CP_COMMIT();
            for (int c = 0; c < 16; c++) {
                int s = c & 1;
                if (c + 1 < 16) {
                    int k0 = (c + 1) * 16, s2b = s ^ 1;
#pragma unroll
                    for (int i = 0; i < 2; i++) {
                        int r = i * 64 + lr;
                        CP_ASYNC16(SADDR(&Asm[s2b * 2560 + r * 20 + lc4]),
                                   &g_Bt[r * 256 + k0 + lc4]);
                        CP_ASYNC16(SADDR(&Bsm[s2b * 2560 + r * 20 + lc4]),
                                   &xbc[(size_t)(pass * 128 + r) * 256 + k0 + lc4]);
                    }
                    CP_COMMIT();
                    CP_WAIT(1);
                } else CP_WAIT(0);
                __syncthreads();
#pragma unroll
                for (int kk = 0; kk < 16; kk += 8) {
                    uint32_t af[4][4], bf[4][2];
#pragma unroll
                    for (int mi = 0; mi < 4; mi++) {
                        int mr = wm * 64 + mi * 16 + gid;
                        af[mi][0] = __float_as_uint(Asm[s * 2560 + mr * 20 + kk + tig]);
                        af[mi][1] = __float_as_uint(Asm[s * 2560 + (mr + 8) * 20 + kk + tig]);
                        af[mi][2] = __float_as_uint(Asm[s * 2560 + mr * 20 + kk + tig + 4]);
                        af[mi][3] = __float_as_uint(Asm[s * 2560 + (mr + 8) * 20 + kk + tig + 4]);
                    }
#pragma unroll
                    for (int ni = 0; ni < 4; ni++) {
                        int nr = wn * 32 + ni * 8 + gid;
                        bf[ni][0] = __float_as_uint(to_tf32(Bsm[s * 2560 + nr * 20 + kk + tig]));
                        bf[ni][1] = __float_as_uint(to_tf32(Bsm[s * 2560 + nr * 20 + kk + tig + 4]));
                    }
#pragma unroll
                    for (int mi = 0; mi < 4; mi++)
#pragma unroll
                        for (int ni = 0; ni < 4; ni++)
                            MMA_TF32(acc[mi][ni][0], acc[mi][ni][1], acc[mi][ni][2], acc[mi][ni][3],
                                     af[mi][0], af[mi][1], af[mi][2], af[mi][3],
                                     bf[ni][0], bf[ni][1]);
                }
                __syncthreads();
            }
            // epilogue -> t1s (tf32-rounded)
#pragma unroll
            for (int mi = 0; mi < 4; mi++) {
                int r0 = wm * 64 + mi * 16 + gid;
#pragma unroll
                for (int ni = 0; ni < 4; ni++) {
                    int cb = pass * 128 + wn * 32 + ni * 8 + tig * 2;
                    *(float2*)&t1s[r0 * 258 + cb] =
                        make_float2(to_tf32(acc[mi][ni][0]), to_tf32(acc[mi][ni][1]));
                    *(float2*)&t1s[(r0 + 8) * 258 + cb] =
                        make_float2(to_tf32(acc[mi][ni][2]), to_tf32(acc[mi][ni][3]));
                }
            }
            __syncthreads();
        }
    }

    // ---------------- F2: T2[128 pe][64 q] = A2 . t1^T  (K=512) ------------
    {
        int wm = warp & 1, wn = warp >> 1;
        float acc[4][2][4];
#pragma unroll
        for (int mi = 0; mi < 4; mi++)
#pragma unroll
            for (int ni = 0; ni < 2; ni++)
#pragma unroll
                for (int r = 0; r < 4; r++) acc[mi][ni][r] = 0.0f;

#pragma unroll
        for (int i = 0; i < 2; i++) {
            int r = i * 64 + lr;
            CP_ASYNC16(SADDR(&Asm[r * 20 + lc4]), &g_A2[r * 512 + lc4]);
        }
        CP_COMMIT();
        for (int c = 0; c < 32; c++) {
            int s = c & 1;
            if (c + 1 < 32) {
                int k0 = (c + 1) * 16, s2b = s ^ 1;
#pragma unroll
                for (int i = 0; i < 2; i++) {
                    int r = i * 64 + lr;
                    CP_ASYNC16(SADDR(&Asm[s2b * 2560 + r * 20 + lc4]),
                               &g_A2[r * 512 + k0 + lc4]);
                }
                CP_COMMIT();
                CP_WAIT(1);
            } else CP_WAIT(0);
            __syncthreads();
            int plane = c >> 4;
            int ck = (c & 15) * 16;
#pragma unroll
            for (int kk = 0; kk < 16; kk += 8) {
                uint32_t af[4][4], bf[2][2];
#pragma unroll
                for (int mi = 0; mi < 4; mi++) {
                    int mr = wm * 64 + mi * 16 + gid;
                    af[mi][0] = __float_as_uint(Asm[s * 2560 + mr * 20 + kk + tig]);
                    af[mi][1] = __float_as_uint(Asm[s * 2560 + (mr + 8) * 20 + kk + tig]);
                    af[mi][2] = __float_as_uint(Asm[s * 2560 + mr * 20 + kk + tig + 4]);
                    af[mi][3] = __float_as_uint(Asm[s * 2560 + (mr + 8) * 20 + kk + tig + 4]);
                }
#pragma unroll
                for (int ni = 0; ni < 2; ni++) {
                    int nq = wn * 16 + ni * 8 + gid;
                    bf[ni][0] = __float_as_uint(t1s[(2 * nq + plane) * 258 + ck + kk + tig]);
                    bf[ni][1] = __float_as_uint(t1s[(2 * nq + plane) * 258 + ck + kk + tig + 4]);
                }
#pragma unroll
                for (int mi = 0; mi < 4; mi++)
#pragma unroll
                    for (int ni = 0; ni < 2; ni++)
                        MMA_TF32(acc[mi][ni][0], acc[mi][ni][1], acc[mi][ni][2], acc[mi][ni][3],
                                 af[mi][0], af[mi][1], af[mi][2], af[mi][3],
                                 bf[ni][0], bf[ni][1]);
            }
            __syncthreads();
        }
#pragma unroll
        for (int mi = 0; mi < 4; mi++) {
            int r0 = wm * 64 + mi * 16 + gid;
#pragma unroll
            for (int ni = 0; ni < 2; ni++) {
                int cb = wn * 16 + ni * 8 + tig * 2;
                *(float2*)&g_T2[(size_t)r0 * 32768 + bc * 64 + cb] =
                    make_float2(acc[mi][ni][0], acc[mi][ni][1]);
                *(float2*)&g_T2[(size_t)(r0 + 8) * 32768 + bc * 64 + cb] =
                    make_float2(acc[mi][ni][2], acc[mi][ni][3]);
            }
        }
    }
}

// ------------- T2 -> T2z: z-branch mode transpose (p<32, q<64) -------------
__global__ __launch_bounds__(256)
void tr_z_k() {
    __shared__ float tile[2][32][65];
    int bc = blockIdx.x;
    int t = threadIdx.x;
#pragma unroll
    for (int i = 0; i < 16; i++) {
        int lin = i * 256 + t;
        int e = lin >> 11, rem = lin & 2047;
        int p = rem >> 6, q = rem & 63;
        tile[e][p][q] = g_T2[(size_t)(2 * p + e) * 32768 + bc * 64 + q];
    }
    __syncthreads();
#pragma unroll
    for (int i = 0; i < 16; i++) {
        int lin = i * 256 + t;
        int e = lin >> 11, rem = lin & 2047;
        int q = rem >> 5, p = rem & 31;
        g_T2z[(size_t)(2 * q + e) * 16384 + bc * 32 + p] = tile[e][p][q];
    }
}

// -------------------- channel mix (both branches, fp32) --------------------
__global__ __launch_bounds__(512)
void mix_k(const float* __restrict__ w1r, const float* __restrict__ w1i,
           const float* __restrict__ w2r, const float* __restrict__ w2i,
           const float* __restrict__ w3r, const float* __restrict__ w3i,
           const float* __restrict__ w4r, const float* __restrict__ w4i) {
    int p  = blockIdx.x;
    int zb = blockIdx.y;
    int pm = p & 31;
    const float *wr, *wi;
    if (!zb) { wr = (p < 32) ? w1r : w2r; wi = (p < 32) ? w1i : w2i; }
    else     { wr = (p < 32) ? w3r : w4r; wi = (p < 32) ? w3i : w4i; }
    float* Sout = g_S2T + (size_t)zb * 128 * 16384;

    int t = threadIdx.x;
    int lane = t & 31;
    int warp = t >> 5;
    __shared__ float2 Ts[16][8][32];
    float2 acc[8][4];
#pragma unroll
    for (int b = 0; b < 8; b++)
#pragma unroll
        for (int j = 0; j < 4; j++) acc[b][j] = make_float2(0.f, 0.f);

    for (int cc = 0; cc < 64; cc += 16) {
#pragma unroll
        for (int i = 0; i < 8; i++) {
            int lin = i * 512 + t;
            int ci_l = lin >> 8;
            int b = (lin >> 5) & 7;
            int q = lin & 31;
            int ci = cc + ci_l;
            float re, im;
            if (!zb) {
                size_t ix = (size_t)(2 * p) * 32768 + ((b * 64 + ci) * 64 + q);
                re = g_T2[ix]; im = g_T2[ix + 32768];
            } else {
                size_t ix = (size_t)(2 * p) * 16384 + ((b * 64 + ci) * 32 + q);
                re = g_T2z[ix]; im = g_T2z[ix + 16384];
            }
            Ts[ci_l][b][q] = make_float2(re, im);
        }
        __syncthreads();
        for (int ci_l = 0; ci_l < 16; ci_l++) {
            int ci = cc + ci_l;
            float wr4[4], wi4[4];
#pragma unroll
            for (int j = 0; j < 4; j++) {
                int co = warp * 4 + j;
                size_t off = ((size_t)(ci * 64 + co) * 32 + pm) * 32 + lane;
                wr4[j] = wr[off];
                wi4[j] = wi[off];
            }
#pragma unroll
            for (int b = 0; b < 8; b++) {
                float2 tv = Ts[ci_l][b][lane];
#pragma unroll
                for (int j = 0; j < 4; j++) {
                    acc[b][j].x = fmaf(tv.x, wr4[j], fmaf(-tv.y, wi4[j], acc[b][j].x));
                    acc[b][j].y = fmaf(tv.x, wi4[j], fmaf( tv.y, wr4[j], acc[b][j].y));
                }
            }
        }
        __syncthreads();
    }
#pragma unroll
    for (int b = 0; b < 8; b++)
#pragma unroll
        for (int j = 0; j < 4; j++) {
            int co = warp * 4 + j;
            size_t n = (size_t)(b * 64 + co) * 32 + lane;
            Sout[(size_t)p * 16384 + n]        = to_tf32(acc[b][j].x);
            Sout[(size_t)(64 + p) * 16384 + n] = to_tf32(acc[b][j].y);
        }
}

// ----------------------- fused I1+I2 (per bco, branch) ---------------------
__global__ __launch_bounds__(256)
void i12_k(float* __restrict__ out) {
    extern __shared__ float sm[];
    float* St  = sm;                    // [128 p'][40]  (cols = k2)
    float* Cs  = St + 128 * 40;         // [256 w][68]
    float* Ys  = Cs + 256 * 68;         // [128 he][34]
    float* Asm = Ys + 128 * 34;         // [2][128][20]
    int t = threadIdx.x;
    int warp = t >> 5, lane = t & 31, gid = lane >> 2, tig = lane & 3;
    int bco = blockIdx.x, zb = blockIdx.y;
    const float* Ssrc = g_S2T + (size_t)zb * 128 * 16384;
    float* outb = out + (size_t)zb * OUTOFF_;
    int lr = t >> 2, lc4 = (t & 3) * 4;

    // load S slice (128 x 32) and Cm table (256 x 64)
#pragma unroll
    for (int i = 0; i < 4; i++) {
        int lin = i * 256 + t;
        int r = lin >> 3, c4 = (lin & 7) * 4;
        *(float4*)&St[r * 40 + c4] = *(const float4*)&Ssrc[(size_t)r * 16384 + bco * 32 + c4];
    }
#pragma unroll
    for (int i = 0; i < 16; i++) {
        int lin = i * 256 + t;
        int r = lin >> 4, c4 = (lin & 15) * 4;
        *(float4*)&Cs[r * 68 + c4] = *(const float4*)&g_CmT2[r * 64 + c4];
    }
    __syncthreads();

    for (int mblk = 0; mblk < 4; mblk++) {
        // ---- I1: Y[128 he][32 k2] = A3[mblk] . S^T  (K=128) ----
        {
            int wm = warp & 3, wn = warp >> 2;
            float acc[2][2][4];
#pragma unroll
            for (int mi = 0; mi < 2; mi++)
#pragma unroll
                for (int ni = 0; ni < 2; ni++)
#pragma unroll
                    for (int r = 0; r < 4; r++) acc[mi][ni][r] = 0.0f;

#pragma unroll
            for (int i = 0; i < 2; i++) {
                int r = i * 64 + lr;
                CP_ASYNC16(SADDR(&Asm[r * 20 + lc4]),
                           &g_A3[(size_t)(mblk * 128 + r) * 128 + lc4]);
            }
            CP_COMMIT();
            for (int c = 0; c < 8; c++) {
                int s = c & 1;
                if (c + 1 < 8) {
                    int k0 = (c + 1) * 16, s2b = s ^ 1;
#pragma unroll
                    for (int i = 0; i < 2; i++) {
                        int r = i * 64 + lr;
                        CP_ASYNC16(SADDR(&Asm[s2b * 2560 + r * 20 + lc4]),
                                   &g_A3[(size_t)(mblk * 128 + r) * 128 + k0 + lc4]);
                    }
                    CP_COMMIT();
                    CP_WAIT(1);
                } else CP_WAIT(0);
                __syncthreads();
#pragma unroll
                for (int kk = 0; kk < 16; kk += 8) {
                    int kg = c * 16 + kk;
                    uint32_t af[2][4], bf[2][2];
#pragma unroll
                    for (int mi = 0; mi < 2; mi++) {
                        int mr = wm * 32 + mi * 16 + gid;
                        af[mi][0] = __float_as_uint(Asm[s * 2560 + mr * 20 + kk + tig]);
                        af[mi][1] = __float_as_uint(Asm[s * 2560 + (mr + 8) * 20 + kk + tig]);
                        af[mi][2] = __float_as_uint(Asm[s * 2560 + mr * 20 + kk + tig + 4]);
                        af[mi][3] = __float_as_uint(Asm[s * 2560 + (mr + 8) * 20 + kk + tig + 4]);
                    }
#pragma unroll
                    for (int ni = 0; ni < 2; ni++) {
                        int n = wn * 16 + ni * 8 + gid;
                        bf[ni][0] = __float_as_uint(St[(kg + tig) * 40 + n]);
                        bf[ni][1] = __float_as_uint(St[(kg + tig + 4) * 40 + n]);
                    }
#pragma unroll
                    for (int mi = 0; mi < 2; mi++)
#pragma unroll
                        for (int ni = 0; ni < 2; ni++)
                            MMA_TF32(acc[mi][ni][0], acc[mi][ni][1], acc[mi][ni][2], acc[mi][ni][3],
                                     af[mi][0], af[mi][1], af[mi][2], af[mi][3],
                                     bf[ni][0], bf[ni][1]);
                }
                __syncthreads();
            }
            // epilogue -> Ys (tf32-rounded)
#pragma unroll
            for (int mi = 0; mi < 2; mi++) {
                int r0 = wm * 32 + mi * 16 + gid;
#pragma unroll
                for (int ni = 0; ni < 2; ni++) {
                    int cb = wn * 16 + ni * 8 + tig * 2;
                    *(float2*)&Ys[r0 * 34 + cb] =
                        make_float2(to_tf32(acc[mi][ni][0]), to_tf32(acc[mi][ni][1]));
                    *(float2*)&Ys[(r0 + 8) * 34 + cb] =
                        make_float2(to_tf32(acc[mi][ni][2]), to_tf32(acc[mi][ni][3]));
                }
            }
        }
        __syncthreads();

        // ---- I2: out[64 h][256 w] = Y . Cm^T  (K=64, all in smem) ----
        {
            int wm = warp & 1, wn = warp >> 1;
            float acc[2][8][4];
#pragma unroll
            for (int mi = 0; mi < 2; mi++)
#pragma unroll
                for (int ni = 0; ni < 8; ni++)
#pragma unroll
                    for (int r = 0; r < 4; r++) acc[mi][ni][r] = 0.0f;

#pragma unroll
            for (int kc = 0; kc < 64; kc += 8) {
                int plane = kc >> 5, kloc = kc & 31;
                uint32_t af[2][4], bf[8][2];
#pragma unroll
                for (int mi = 0; mi < 2; mi++) {
                    int mr = wm * 32 + mi * 16 + gid;
                    af[mi][0] = __float_as_uint(Ys[(2 * mr + plane) * 34 + kloc + tig]);
                    af[mi][1] = __float_as_uint(Ys[(2 * (mr + 8) + plane) * 34 + kloc + tig]);
                    af[mi][2] = __float_as_uint(Ys[(2 * mr + plane) * 34 + kloc + tig + 4]);
                    af[mi][3] = __float_as_uint(Ys[(2 * (mr + 8) + plane) * 34 + kloc + tig + 4]);
                }
#pragma unroll
                for (int ni = 0; ni < 8; ni++) {
                    int n = wn * 64 + ni * 8 + gid;
                    bf[ni][0] = __float_as_uint(Cs[n * 68 + kc + tig]);
                    bf[ni][1] = __float_as_uint(Cs[n * 68 + kc + tig + 4]);
                }
#pragma unroll
                for (int mi = 0; mi < 2; mi++)
#pragma unroll
                    for (int ni = 0; ni < 8; ni++)
                        MMA_TF32(acc[mi][ni][0], acc[mi][ni][1], acc[mi][ni][2], acc[mi][ni][3],
                                 af[mi][0], af[mi][1], af[mi][2], af[mi][3],
                                 bf[ni][0], bf[ni][1]);
            }
#pragma unroll
            for (int mi = 0; mi < 2; mi++) {
                int h = mblk * 64 + wm * 32 + mi * 16 + gid;
                size_t r0 = ((size_t)bco * 256 + h) * 256;
                size_t r8 = ((size_t)bco * 256 + h + 8) * 256;
#pragma unroll
                for (int ni = 0; ni < 8; ni++) {
                    int w = wn * 64 + ni * 8 + tig * 2;
                    *(float2*)&outb[r0 + w] = make_float2(acc[mi][ni][0], acc[mi][ni][1]);
                    *(float2*)&outb[r8 + w] = make_float2(acc[mi][ni][2], acc[mi][ni][3]);
                }
            }
        }
        __syncthreads();
    }
}

// ------------------------------- launcher ----------------------------------
extern "C" void kernel_launch(void* const* d_in, const int* in_sizes, int n_in,
                              void* d_out, int out_size) {
    const float* x   = (const float*)d_in[0];
    const float* w1r = (const float*)d_in[1];
    const float* w1i = (const float*)d_in[2];
    const float* w2r = (const float*)d_in[3];
    const float* w2i = (const float*)d_in[4];
    const float* w3r = (const float*)d_in[5];
    const float* w3i = (const float*)d_in[6];
    const float* w4r = (const float*)d_in[7];
    const float* w4i = (const float*)d_in[8];
    float* out = (float*)d_out;

    cudaFuncSetAttribute(f12_k, cudaFuncAttributeMaxDynamicSharedMemorySize, F12_SMEM);
    cudaFuncSetAttribute(i12_k, cudaFuncAttributeMaxDynamicSharedMemorySize, I12_SMEM);

    init_tables_k<<<64, 256>>>();
    f12_k<<<512, 256, F12_SMEM>>>(x);
    tr_z_k<<<512, 256>>>();
    mix_k<<<dim3(64, 2), 512>>>(w1r, w1i, w2r, w2i, w3r, w3i, w4r, w4i);
    i12_k<<<dim3(512, 2), 256, I12_SMEM>>>(out);
}

// round 9
// speedup vs baseline: 1.6017x; 1.6017x over previous
#include <cuda_runtime.h>
#include <cstdint>

// ---------------------------------------------------------------------------
// SpectralConv2d (FNO) without FFT: whole pipeline as tf32 mma.sync GEMMs with
// dense (coalesced) operand layouts everywhere. (R7 structure; mix co-split.)
//   F1 : t1R[bc][q][e][h]      = Bt(128x256) . x^T        (EPI1 relayout)
//   F2 : T2 [2p+e][bc*64+q]    = A2(128x512) . t1R^T      (plain)
//   trz: T2z[2q+e][bc*32+p]    (z-branch mode transpose, p<32)
//   mix: fp32 FFMA, grid (64 p, 2 branch, 2 co-half) for occupancy
//   trs: S2[n][128] = S2T^T    (I1 B operand)
//   I1 : Y2R[bco*256+h][e*32+k2] = A3(512x128) . S2^T     (EPI2 relayout)
//   I2 : out = Y2R . CmT2^T                                (plain)
// ---------------------------------------------------------------------------

namespace {
constexpr int ROWS_   = 131072;      // B*C*H
constexpr int OUTOFF_ = 33554432;    // B*COUT*H*W
}

// ------------------------- static device scratch ---------------------------
__device__ __align__(16) float g_Bt  [128 * 256];
__device__ __align__(16) float g_A2  [128 * 512];
__device__ __align__(16) float g_A3  [512 * 128];
__device__ __align__(16) float g_CmT2[256 * 64];
__device__ __align__(16) float g_t1R [512 * 32768];      // 64MB
__device__ __align__(16) float g_T2  [128 * 32768];      // 16MB
__device__ __align__(16) float g_T2z [128 * 16384];      // 8MB
__device__ __align__(16) float g_S2T [2 * 128 * 16384];  // 16MB (plane-major)
__device__ __align__(16) float g_S2  [2 * 16384 * 128];  // 16MB (row-major, I1 B)
__device__ __align__(16) float g_Y2R [2 * 131072 * 64];  // 67MB

// ------------------------------ helpers ------------------------------------
__device__ __forceinline__ float to_tf32(float x) {
    float r; asm("cvt.rna.tf32.f32 %0, %1;" : "=f"(r) : "f"(x)); return r;
}
#define CP_ASYNC16(dst_u32, src_ptr) \
    asm volatile("cp.async.cg.shared.global [%0], [%1], 16;" :: "r"(dst_u32), "l"(src_ptr))
#define CP_COMMIT() asm volatile("cp.async.commit_group;")
#define CP_WAIT(n)  asm volatile("cp.async.wait_group %0;" :: "n"(n))

#define MMA_TF32(d0,d1,d2,d3, a0,a1,a2,a3, b0,b1)                                   \
    asm volatile("mma.sync.aligned.m16n8k8.row.col.f32.tf32.tf32.f32 "              \
        "{%0,%1,%2,%3}, {%4,%5,%6,%7}, {%8,%9}, {%0,%1,%2,%3};"                     \
        : "+f"(d0), "+f"(d1), "+f"(d2), "+f"(d3)                                    \
        : "r"(a0), "r"(a1), "r"(a2), "r"(a3), "r"(b0), "r"(b1))

// ------------------------------ table init --------------------------------
__global__ void init_tables_k() {
    int t = blockIdx.x * blockDim.x + threadIdx.x;
    if (t >= 64 * 256) return;
    int m = t >> 8, n = t & 255;
    int mf = (m < 32) ? m : m + 192;
    int k = (mf * n) & 255;
    float s, c;
    sincospif((float)k * (1.0f / 128.0f), &s, &c);
    float tc = to_tf32(c), ts = to_tf32(s), tns = to_tf32(-s);

    g_Bt[(2 * m) * 256 + n]     = tc;
    g_Bt[(2 * m + 1) * 256 + n] = tns;
    g_A2[(2 * m) * 512 + n]           = tc;
    g_A2[(2 * m) * 512 + 256 + n]     = ts;
    g_A2[(2 * m + 1) * 512 + n]       = tns;
    g_A2[(2 * m + 1) * 512 + 256 + n] = tc;
    g_A3[(2 * n) * 128 + m]          = tc;
    g_A3[(2 * n) * 128 + 64 + m]     = tns;
    g_A3[(2 * n + 1) * 128 + m]      = ts;
    g_A3[(2 * n + 1) * 128 + 64 + m] = tc;

    int k2 = m & 31;
    int kk = (k2 * n) & 255;
    float s2, c2;
    sincospif((float)kk * (1.0f / 128.0f), &s2, &c2);
    const float sc = 1.0f / 65536.0f;
    float v;
    if (m < 32) v = (k2 == 0) ? sc : 2.0f * sc * c2;
    else        v = (k2 == 0) ? 0.0f : -2.0f * sc * s2;
    g_CmT2[n * 64 + m] = to_tf32(v);
}

// -------------------- tf32 mma.sync GEMM -----------------------------------
template<int EPI>
__device__ __forceinline__ void epi_store(float* C, size_t r0, size_t cb, int ldc,
                                          float v0, float v1) {
    size_t addr;
    if (EPI == 0)      addr = r0 * (size_t)ldc + cb;
    else if (EPI == 1) addr = (cb >> 8) * 32768 + (r0 >> 1) * 512 + (r0 & 1) * 256 + (cb & 255);
    else               addr = ((cb >> 5) * 256 + (r0 >> 1)) * 64 + (r0 & 1) * 32 + (cb & 31);
    *(float2*)&C[addr] = make_float2(v0, v1);
}

template<int CVTB, int CVTC, int EPI>
__global__ __launch_bounds__(256)
void gemm_tc(const float* __restrict__ A, const float* __restrict__ Bt,
             float* __restrict__ C, int K, int ldc) {
    __shared__ float As[2][128][20];
    __shared__ float Bs[2][128][20];
    int t = threadIdx.x;
    int warp = t >> 5, lane = t & 31;
    int gid = lane >> 2, tig = lane & 3;
    int wm = warp & 1, wn = warp >> 1;
    size_t m0 = (size_t)blockIdx.x * 128;
    size_t n0 = (size_t)blockIdx.y * 128;
    int nK = K >> 4;

    float acc[4][4][4];
#pragma unroll
    for (int mi = 0; mi < 4; mi++)
#pragma unroll
        for (int ni = 0; ni < 4; ni++)
#pragma unroll
            for (int r = 0; r < 4; r++) acc[mi][ni][r] = 0.0f;

    int lr  = t >> 2;
    int lc4 = (t & 3) * 4;

    auto load_stage = [&](int s, int k0) {
#pragma unroll
        for (int i = 0; i < 2; i++) {
            int r = i * 64 + lr;
            uint32_t da = (uint32_t)__cvta_generic_to_shared(&As[s][r][lc4]);
            CP_ASYNC16(da, &A[(m0 + r) * K + k0 + lc4]);
            uint32_t db = (uint32_t)__cvta_generic_to_shared(&Bs[s][r][lc4]);
            CP_ASYNC16(db, &Bt[(n0 + r) * K + k0 + lc4]);
        }
        CP_COMMIT();
    };

    load_stage(0, 0);
    for (int k0 = 0; k0 < nK; k0++) {
        int s = k0 & 1;
        if (k0 + 1 < nK) { load_stage(s ^ 1, (k0 + 1) << 4); CP_WAIT(1); }
        else             { CP_WAIT(0); }
        __syncthreads();
#pragma unroll
        for (int kk = 0; kk < 16; kk += 8) {
            uint32_t af[4][4], bf[4][2];
#pragma unroll
            for (int mi = 0; mi < 4; mi++) {
                int mr = wm * 64 + mi * 16 + gid;
                af[mi][0] = __float_as_uint(As[s][mr][kk + tig]);
                af[mi][1] = __float_as_uint(As[s][mr + 8][kk + tig]);
                af[mi][2] = __float_as_uint(As[s][mr][kk + tig + 4]);
                af[mi][3] = __float_as_uint(As[s][mr + 8][kk + tig + 4]);
            }
#pragma unroll
            for (int ni = 0; ni < 4; ni++) {
                int nr = wn * 32 + ni * 8 + gid;
                float b0 = Bs[s][nr][kk + tig], b1 = Bs[s][nr][kk + tig + 4];
                if (CVTB) { b0 = to_tf32(b0); b1 = to_tf32(b1); }
                bf[ni][0] = __float_as_uint(b0);
                bf[ni][1] = __float_as_uint(b1);
            }
#pragma unroll
            for (int mi = 0; mi < 4; mi++)
#pragma unroll
                for (int ni = 0; ni < 4; ni++)
                    MMA_TF32(acc[mi][ni][0], acc[mi][ni][1], acc[mi][ni][2], acc[mi][ni][3],
                             af[mi][0], af[mi][1], af[mi][2], af[mi][3],
                             bf[ni][0], bf[ni][1]);
        }
        __syncthreads();
    }

#pragma unroll
    for (int mi = 0; mi < 4; mi++) {
        size_t r0 = m0 + wm * 64 + mi * 16 + gid;
#pragma unroll
        for (int ni = 0; ni < 4; ni++) {
            size_t cb = n0 + wn * 32 + ni * 8 + tig * 2;
            float v0 = acc[mi][ni][0], v1 = acc[mi][ni][1];
            float v2 = acc[mi][ni][2], v3 = acc[mi][ni][3];
            if (CVTC) { v0 = to_tf32(v0); v1 = to_tf32(v1); v2 = to_tf32(v2); v3 = to_tf32(v3); }
            epi_store<EPI>(C, r0,     cb, ldc, v0, v1);
            epi_store<EPI>(C, r0 + 8, cb, ldc, v2, v3);
        }
    }
}

// ------------- T2 -> T2z: z-branch mode transpose (p<32, q<64) -------------
__global__ __launch_bounds__(256)
void tr_z_k() {
    __shared__ float tile[2][32][65];
    int bc = blockIdx.x;
    int t = threadIdx.x;
#pragma unroll
    for (int i = 0; i < 16; i++) {
        int lin = i * 256 + t;
        int e = lin >> 11, rem = lin & 2047;
        int p = rem >> 6, q = rem & 63;
        tile[e][p][q] = g_T2[(size_t)(2 * p + e) * 32768 + bc * 64 + q];
    }
    __syncthreads();
#pragma unroll
    for (int i = 0; i < 16; i++) {
        int lin = i * 256 + t;
        int e = lin >> 11, rem = lin & 2047;
        int q = rem >> 5, p = rem & 31;
        g_T2z[(size_t)(2 * q + e) * 16384 + bc * 32 + p] = tile[e][p][q];
    }
}

// ----------------- S2T (plane-major) -> S2 (row-major, I1 B) ---------------
__global__ void tr_s_k() {
    __shared__ float tile[32][33];
    int zb = blockIdx.z;
    int n0 = blockIdx.x * 32, p0 = blockIdx.y * 32;
    const float* src = g_S2T + (size_t)zb * 128 * 16384;
    float* dst = g_S2 + (size_t)zb * 16384 * 128;
    int tx = threadIdx.x, ty = threadIdx.y;
#pragma unroll
    for (int k = 0; k < 32; k += 8)
        tile[ty + k][tx] = src[(size_t)(p0 + ty + k) * 16384 + n0 + tx];
    __syncthreads();
#pragma unroll
    for (int k = 0; k < 32; k += 8)
        dst[(size_t)(n0 + ty + k) * 128 + p0 + tx] = tile[tx][ty + k];
}

// -------------------- channel mix (co-split for occupancy) -----------------
// grid (64 p, 2 branch, 2 co-half); each warp handles 2 co values.
__global__ __launch_bounds__(512)
void mix_k(const float* __restrict__ w1r, const float* __restrict__ w1i,
           const float* __restrict__ w2r, const float* __restrict__ w2i,
           const float* __restrict__ w3r, const float* __restrict__ w3i,
           const float* __restrict__ w4r, const float* __restrict__ w4i) {
    int p  = blockIdx.x;
    int zb = blockIdx.y;
    int cog = blockIdx.z;            // co half: 0 -> co 0..31, 1 -> co 32..63
    int pm = p & 31;
    const float *wr, *wi;
    if (!zb) { wr = (p < 32) ? w1r : w2r; wi = (p < 32) ? w1i : w2i; }
    else     { wr = (p < 32) ? w3r : w4r; wi = (p < 32) ? w3i : w4i; }
    float* Sout = g_S2T + (size_t)zb * 128 * 16384;

    int t = threadIdx.x;
    int lane = t & 31;
    int warp = t >> 5;               // 16 warps -> co = cog*32 + warp*2 + j
    __shared__ float2 Ts[16][8][32];
    float2 acc[8][2];
#pragma unroll
    for (int b = 0; b < 8; b++)
#pragma unroll
        for (int j = 0; j < 2; j++) acc[b][j] = make_float2(0.f, 0.f);

    for (int cc = 0; cc < 64; cc += 16) {
#pragma unroll
        for (int i = 0; i < 8; i++) {
            int lin = i * 512 + t;
            int ci_l = lin >> 8;
            int b = (lin >> 5) & 7;
            int q = lin & 31;
            int ci = cc + ci_l;
            float re, im;
            if (!zb) {
                size_t ix = (size_t)(2 * p) * 32768 + ((b * 64 + ci) * 64 + q);
                re = g_T2[ix]; im = g_T2[ix + 32768];
            } else {
                size_t ix = (size_t)(2 * p) * 16384 + ((b * 64 + ci) * 32 + q);
                re = g_T2z[ix]; im = g_T2z[ix + 16384];
            }
            Ts[ci_l][b][q] = make_float2(re, im);
        }
        __syncthreads();
        for (int ci_l = 0; ci_l < 16; ci_l++) {
            int ci = cc + ci_l;
            float wr2[2], wi2[2];
#pragma unroll
            for (int j = 0; j < 2; j++) {
                int co = cog * 32 + warp * 2 + j;
                size_t off = ((size_t)(ci * 64 + co) * 32 + pm) * 32 + lane;
                wr2[j] = wr[off];
                wi2[j] = wi[off];
            }
#pragma unroll
            for (int b = 0; b < 8; b++) {
                float2 tv = Ts[ci_l][b][lane];
#pragma unroll
                for (int j = 0; j < 2; j++) {
                    acc[b][j].x = fmaf(tv.x, wr2[j], fmaf(-tv.y, wi2[j], acc[b][j].x));
                    acc[b][j].y = fmaf(tv.x, wi2[j], fmaf( tv.y, wr2[j], acc[b][j].y));
                }
            }
        }
        __syncthreads();
    }
#pragma unroll
    for (int b = 0; b < 8; b++)
#pragma unroll
        for (int j = 0; j < 2; j++) {
            int co = cog * 32 + warp * 2 + j;
            size_t n = (size_t)(b * 64 + co) * 32 + lane;
            Sout[(size_t)p * 16384 + n]        = to_tf32(acc[b][j].x);
            Sout[(size_t)(64 + p) * 16384 + n] = to_tf32(acc[b][j].y);
        }
}

// ------------------------------- launcher ----------------------------------
extern "C" void kernel_launch(void* const* d_in, const int* in_sizes, int n_in,
                              void* d_out, int out_size) {
    const float* x   = (const float*)d_in[0];
    const float* w1r = (const float*)d_in[1];
    const float* w1i = (const float*)d_in[2];
    const float* w2r = (const float*)d_in[3];
    const float* w2i = (const float*)d_in[4];
    const float* w3r = (const float*)d_in[5];
    const float* w3i = (const float*)d_in[6];
    const float* w4r = (const float*)d_in[7];
    const float* w4i = (const float*)d_in[8];
    float* out = (float*)d_out;

    float *pBt, *pA2, *pA3, *pCmT2, *pT1R, *pT2, *pS2, *pY2R;
    cudaGetSymbolAddress((void**)&pBt,   g_Bt);
    cudaGetSymbolAddress((void**)&pA2,   g_A2);
    cudaGetSymbolAddress((void**)&pA3,   g_A3);
    cudaGetSymbolAddress((void**)&pCmT2, g_CmT2);
    cudaGetSymbolAddress((void**)&pT1R,  g_t1R);
    cudaGetSymbolAddress((void**)&pT2,   g_T2);
    cudaGetSymbolAddress((void**)&pS2,   g_S2);
    cudaGetSymbolAddress((void**)&pY2R,  g_Y2R);

    init_tables_k<<<64, 256>>>();

    // F1: t1R = Bt . x^T   (M=128, N=131072, K=256)
    gemm_tc<1, 1, 1><<<dim3(1, 1024), 256>>>(pBt, x, pT1R, 256, 0);

    // F2: T2 = A2 . t1R^T  (M=128, N=32768, K=512)
    gemm_tc<0, 0, 0><<<dim3(1, 256), 256>>>(pA2, pT1R, pT2, 512, 32768);

    // z-branch mode transpose
    tr_z_k<<<512, 256>>>();

    // channel mix (fp32), co-split grid for occupancy
    mix_k<<<dim3(64, 2, 2), 512>>>(w1r, w1i, w2r, w2i, w3r, w3i, w4r, w4i);

    // S2T -> S2 row-major
    tr_s_k<<<dim3(512, 4, 2), dim3(32, 8)>>>();

    // I1: Y2R = A3 . S2^T  (M=512, N=16384, K=128), per branch
    gemm_tc<0, 1, 2><<<dim3(4, 128), 256>>>(pA3, pS2,               pY2R,                128, 0);
    gemm_tc<0, 1, 2><<<dim3(4, 128), 256>>>(pA3, pS2 + 16384 * 128, pY2R + 131072 * 64,  128, 0);

    // I2: out = Y2R . CmT2^T (M=131072, N=256, K=64), per branch
    gemm_tc<0, 0, 0><<<dim3(1024, 2), 256>>>(pY2R,               pCmT2, out,           64, 256);
    gemm_tc<0, 0, 0><<<dim3(1024, 2), 256>>>(pY2R + 131072 * 64, pCmT2, out + OUTOFF_, 64, 256);
}

// round 10
// speedup vs baseline: 1.7040x; 1.0639x over previous
#include <cuda_runtime.h>
#include <cstdint>

// ---------------------------------------------------------------------------
// SpectralConv2d (FNO) without FFT: whole pipeline as tf32 mma.sync GEMMs with
// dense (coalesced) operand layouts. R7 structure; mix uses per-warp cp.async
// weight staging (2-stage smem ring) to decouple the 134MB weight stream from
// FFMA consumption at 1-CTA/SM occupancy.
// ---------------------------------------------------------------------------

namespace {
constexpr int ROWS_   = 131072;      // B*C*H
constexpr int OUTOFF_ = 33554432;    // B*COUT*H*W
}

// ------------------------- static device scratch ---------------------------
__device__ __align__(16) float g_Bt  [128 * 256];
__device__ __align__(16) float g_A2  [128 * 512];
__device__ __align__(16) float g_A3  [512 * 128];
__device__ __align__(16) float g_CmT2[256 * 64];
__device__ __align__(16) float g_t1R [512 * 32768];      // 64MB
__device__ __align__(16) float g_T2  [128 * 32768];      // 16MB
__device__ __align__(16) float g_T2z [128 * 16384];      // 8MB
__device__ __align__(16) float g_S2T [2 * 128 * 16384];  // 16MB (plane-major)
__device__ __align__(16) float g_S2  [2 * 16384 * 128];  // 16MB (row-major, I1 B)
__device__ __align__(16) float g_Y2R [2 * 131072 * 64];  // 67MB

// ------------------------------ helpers ------------------------------------
__device__ __forceinline__ float to_tf32(float x) {
    float r; asm("cvt.rna.tf32.f32 %0, %1;" : "=f"(r) : "f"(x)); return r;
}
#define CP_ASYNC16(dst_u32, src_ptr) \
    asm volatile("cp.async.cg.shared.global [%0], [%1], 16;" :: "r"(dst_u32), "l"(src_ptr))
#define CP_COMMIT() asm volatile("cp.async.commit_group;")
#define CP_WAIT(n)  asm volatile("cp.async.wait_group %0;" :: "n"(n))
#define SADDR(p) ((uint32_t)__cvta_generic_to_shared(p))

#define MMA_TF32(d0,d1,d2,d3, a0,a1,a2,a3, b0,b1)                                   \
    asm volatile("mma.sync.aligned.m16n8k8.row.col.f32.tf32.tf32.f32 "              \
        "{%0,%1,%2,%3}, {%4,%5,%6,%7}, {%8,%9}, {%0,%1,%2,%3};"                     \
        : "+f"(d0), "+f"(d1), "+f"(d2), "+f"(d3)                                    \
        : "r"(a0), "r"(a1), "r"(a2), "r"(a3), "r"(b0), "r"(b1))

// ------------------------------ table init --------------------------------
__global__ void init_tables_k() {
    int t = blockIdx.x * blockDim.x + threadIdx.x;
    if (t >= 64 * 256) return;
    int m = t >> 8, n = t & 255;
    int mf = (m < 32) ? m : m + 192;
    int k = (mf * n) & 255;
    float s, c;
    sincospif((float)k * (1.0f / 128.0f), &s, &c);
    float tc = to_tf32(c), ts = to_tf32(s), tns = to_tf32(-s);

    g_Bt[(2 * m) * 256 + n]     = tc;
    g_Bt[(2 * m + 1) * 256 + n] = tns;
    g_A2[(2 * m) * 512 + n]           = tc;
    g_A2[(2 * m) * 512 + 256 + n]     = ts;
    g_A2[(2 * m + 1) * 512 + n]       = tns;
    g_A2[(2 * m + 1) * 512 + 256 + n] = tc;
    g_A3[(2 * n) * 128 + m]          = tc;
    g_A3[(2 * n) * 128 + 64 + m]     = tns;
    g_A3[(2 * n + 1) * 128 + m]      = ts;
    g_A3[(2 * n + 1) * 128 + 64 + m] = tc;

    int k2 = m & 31;
    int kk = (k2 * n) & 255;
    float s2, c2;
    sincospif((float)kk * (1.0f / 128.0f), &s2, &c2);
    const float sc = 1.0f / 65536.0f;
    float v;
    if (m < 32) v = (k2 == 0) ? sc : 2.0f * sc * c2;
    else        v = (k2 == 0) ? 0.0f : -2.0f * sc * s2;
    g_CmT2[n * 64 + m] = to_tf32(v);
}

// -------------------- tf32 mma.sync GEMM -----------------------------------
template<int EPI>
__device__ __forceinline__ void epi_store(float* C, size_t r0, size_t cb, int ldc,
                                          float v0, float v1) {
    size_t addr;
    if (EPI == 0)      addr = r0 * (size_t)ldc + cb;
    else if (EPI == 1) addr = (cb >> 8) * 32768 + (r0 >> 1) * 512 + (r0 & 1) * 256 + (cb & 255);
    else               addr = ((cb >> 5) * 256 + (r0 >> 1)) * 64 + (r0 & 1) * 32 + (cb & 31);
    *(float2*)&C[addr] = make_float2(v0, v1);
}

template<int CVTB, int CVTC, int EPI>
__global__ __launch_bounds__(256)
void gemm_tc(const float* __restrict__ A, const float* __restrict__ Bt,
             float* __restrict__ C, int K, int ldc) {
    __shared__ float As[2][128][20];
    __shared__ float Bs[2][128][20];
    int t = threadIdx.x;
    int warp = t >> 5, lane = t & 31;
    int gid = lane >> 2, tig = lane & 3;
    int wm = warp & 1, wn = warp >> 1;
    size_t m0 = (size_t)blockIdx.x * 128;
    size_t n0 = (size_t)blockIdx.y * 128;
    int nK = K >> 4;

    float acc[4][4][4];
#pragma unroll
    for (int mi = 0; mi < 4; mi++)
#pragma unroll
        for (int ni = 0; ni < 4; ni++)
#pragma unroll
            for (int r = 0; r < 4; r++) acc[mi][ni][r] = 0.0f;

    int lr  = t >> 2;
    int lc4 = (t & 3) * 4;

    auto load_stage = [&](int s, int k0) {
#pragma unroll
        for (int i = 0; i < 2; i++) {
            int r = i * 64 + lr;
            uint32_t da = (uint32_t)__cvta_generic_to_shared(&As[s][r][lc4]);
            CP_ASYNC16(da, &A[(m0 + r) * K + k0 + lc4]);
            uint32_t db = (uint32_t)__cvta_generic_to_shared(&Bs[s][r][lc4]);
            CP_ASYNC16(db, &Bt[(n0 + r) * K + k0 + lc4]);
        }
        CP_COMMIT();
    };

    load_stage(0, 0);
    for (int k0 = 0; k0 < nK; k0++) {
        int s = k0 & 1;
        if (k0 + 1 < nK) { load_stage(s ^ 1, (k0 + 1) << 4); CP_WAIT(1); }
        else             { CP_WAIT(0); }
        __syncthreads();
#pragma unroll
        for (int kk = 0; kk < 16; kk += 8) {
            uint32_t af[4][4], bf[4][2];
#pragma unroll
            for (int mi = 0; mi < 4; mi++) {
                int mr = wm * 64 + mi * 16 + gid;
                af[mi][0] = __float_as_uint(As[s][mr][kk + tig]);
                af[mi][1] = __float_as_uint(As[s][mr + 8][kk + tig]);
                af[mi][2] = __float_as_uint(As[s][mr][kk + tig + 4]);
                af[mi][3] = __float_as_uint(As[s][mr + 8][kk + tig + 4]);
            }
#pragma unroll
            for (int ni = 0; ni < 4; ni++) {
                int nr = wn * 32 + ni * 8 + gid;
                float b0 = Bs[s][nr][kk + tig], b1 = Bs[s][nr][kk + tig + 4];
                if (CVTB) { b0 = to_tf32(b0); b1 = to_tf32(b1); }
                bf[ni][0] = __float_as_uint(b0);
                bf[ni][1] = __float_as_uint(b1);
            }
#pragma unroll
            for (int mi = 0; mi < 4; mi++)
#pragma unroll
                for (int ni = 0; ni < 4; ni++)
                    MMA_TF32(acc[mi][ni][0], acc[mi][ni][1], acc[mi][ni][2], acc[mi][ni][3],
                             af[mi][0], af[mi][1], af[mi][2], af[mi][3],
                             bf[ni][0], bf[ni][1]);
        }
        __syncthreads();
    }

#pragma unroll
    for (int mi = 0; mi < 4; mi++) {
        size_t r0 = m0 + wm * 64 + mi * 16 + gid;
#pragma unroll
        for (int ni = 0; ni < 4; ni++) {
            size_t cb = n0 + wn * 32 + ni * 8 + tig * 2;
            float v0 = acc[mi][ni][0], v1 = acc[mi][ni][1];
            float v2 = acc[mi][ni][2], v3 = acc[mi][ni][3];
            if (CVTC) { v0 = to_tf32(v0); v1 = to_tf32(v1); v2 = to_tf32(v2); v3 = to_tf32(v3); }
            epi_store<EPI>(C, r0,     cb, ldc, v0, v1);
            epi_store<EPI>(C, r0 + 8, cb, ldc, v2, v3);
        }
    }
}

// ------------- T2 -> T2z: z-branch mode transpose (p<32, q<64) -------------
__global__ __launch_bounds__(256)
void tr_z_k() {
    __shared__ float tile[2][32][65];
    int bc = blockIdx.x;
    int t = threadIdx.x;
#pragma unroll
    for (int i = 0; i < 16; i++) {
        int lin = i * 256 + t;
        int e = lin >> 11, rem = lin & 2047;
        int p = rem >> 6, q = rem & 63;
        tile[e][p][q] = g_T2[(size_t)(2 * p + e) * 32768 + bc * 64 + q];
    }
    __syncthreads();
#pragma unroll
    for (int i = 0; i < 16; i++) {
        int lin = i * 256 + t;
        int e = lin >> 11, rem = lin & 2047;
        int q = rem >> 5, p = rem & 31;
        g_T2z[(size_t)(2 * q + e) * 16384 + bc * 32 + p] = tile[e][p][q];
    }
}

// ----------------- S2T (plane-major) -> S2 (row-major, I1 B) ---------------
__global__ void tr_s_k() {
    __shared__ float tile[32][33];
    int zb = blockIdx.z;
    int n0 = blockIdx.x * 32, p0 = blockIdx.y * 32;
    const float* src = g_S2T + (size_t)zb * 128 * 16384;
    float* dst = g_S2 + (size_t)zb * 16384 * 128;
    int tx = threadIdx.x, ty = threadIdx.y;
#pragma unroll
    for (int k = 0; k < 32; k += 8)
        tile[ty + k][tx] = src[(size_t)(p0 + ty + k) * 16384 + n0 + tx];
    __syncthreads();
#pragma unroll
    for (int k = 0; k < 32; k += 8)
        dst[(size_t)(n0 + ty + k) * 128 + p0 + tx] = tile[tx][ty + k];
}

// ---------------- channel mix (cp.async weight staging) --------------------
// grid (64 p, 2 branch); 16 warps, warp -> co = warp*4+j, lane -> k2.
// Each warp stages its 1KB/ci weight slab into a private 2-stage smem ring.
__global__ __launch_bounds__(512)
void mix_k(const float* __restrict__ w1r, const float* __restrict__ w1i,
           const float* __restrict__ w2r, const float* __restrict__ w2i,
           const float* __restrict__ w3r, const float* __restrict__ w3i,
           const float* __restrict__ w4r, const float* __restrict__ w4i) {
    int p  = blockIdx.x;
    int zb = blockIdx.y;
    int pm = p & 31;
    const float *wr, *wi;
    if (!zb) { wr = (p < 32) ? w1r : w2r; wi = (p < 32) ? w1i : w2i; }
    else     { wr = (p < 32) ? w3r : w4r; wi = (p < 32) ? w3i : w4i; }
    float* Sout = g_S2T + (size_t)zb * 128 * 16384;

    int t = threadIdx.x;
    int lane = t & 31;
    int warp = t >> 5;
    __shared__ float2 Ts[8][8][32];        // 16KB: 8-ci chunk of T2 data
    __shared__ float  Wst[16][2][256];     // 32KB: per-warp 2-stage weight ring
    float2 acc[8][4];
#pragma unroll
    for (int b = 0; b < 8; b++)
#pragma unroll
        for (int j = 0; j < 4; j++) acc[b][j] = make_float2(0.f, 0.f);

    int j_ld = lane >> 3;            // 0..3
    int l4   = (lane & 7) * 4;       // 0,4,...,28

    auto load_ts = [&](int cc) {
#pragma unroll
        for (int i = 0; i < 4; i++) {
            int lin = i * 512 + t;
            int ci_l = lin >> 8;             // 0..7
            int b = (lin >> 5) & 7;
            int q = lin & 31;
            int ci = cc + ci_l;
            float re, im;
            if (!zb) {
                size_t ix = (size_t)(2 * p) * 32768 + ((b * 64 + ci) * 64 + q);
                re = g_T2[ix]; im = g_T2[ix + 32768];
            } else {
                size_t ix = (size_t)(2 * p) * 16384 + ((b * 64 + ci) * 32 + q);
                re = g_T2z[ix]; im = g_T2z[ix + 16384];
            }
            Ts[ci_l][b][q] = make_float2(re, im);
        }
    };

    auto stage_w = [&](int st, int ci) {
        size_t off = ((size_t)(ci * 64 + warp * 4 + j_ld) * 32 + pm) * 32 + l4;
        CP_ASYNC16(SADDR(&Wst[warp][st][j_ld * 32 + l4]), wr + off);
        CP_ASYNC16(SADDR(&Wst[warp][st][128 + j_ld * 32 + l4]), wi + off);
        CP_COMMIT();
    };

    load_ts(0);
    __syncthreads();
    stage_w(0, 0);

    for (int ci = 0; ci < 64; ci++) {
        int st = ci & 1;
        __syncwarp();                         // all reads of buffer st^1 done
        if (ci + 1 < 64) { stage_w(st ^ 1, ci + 1); CP_WAIT(1); }
        else             { CP_WAIT(0); }
        __syncwarp();                         // stage st visible warp-wide

        float wr4[4], wi4[4];
#pragma unroll
        for (int j = 0; j < 4; j++) {
            wr4[j] = Wst[warp][st][j * 32 + lane];
            wi4[j] = Wst[warp][st][128 + j * 32 + lane];
        }
        int ci_l = ci & 7;
#pragma unroll
        for (int b = 0; b < 8; b++) {
            float2 tv = Ts[ci_l][b][lane];
#pragma unroll
            for (int j = 0; j < 4; j++) {
                acc[b][j].x = fmaf(tv.x, wr4[j], fmaf(-tv.y, wi4[j], acc[b][j].x));
                acc[b][j].y = fmaf(tv.x, wi4[j], fmaf( tv.y, wr4[j], acc[b][j].y));
            }
        }
        if (ci_l == 7 && ci + 1 < 64) {
            __syncthreads();
            load_ts(ci + 1);
            __syncthreads();
        }
    }

#pragma unroll
    for (int b = 0; b < 8; b++)
#pragma unroll
        for (int j = 0; j < 4; j++) {
            int co = warp * 4 + j;
            size_t n = (size_t)(b * 64 + co) * 32 + lane;
            Sout[(size_t)p * 16384 + n]        = to_tf32(acc[b][j].x);
            Sout[(size_t)(64 + p) * 16384 + n] = to_tf32(acc[b][j].y);
        }
}

// ------------------------------- launcher ----------------------------------
extern "C" void kernel_launch(void* const* d_in, const int* in_sizes, int n_in,
                              void* d_out, int out_size) {
    const float* x   = (const float*)d_in[0];
    const float* w1r = (const float*)d_in[1];
    const float* w1i = (const float*)d_in[2];
    const float* w2r = (const float*)d_in[3];
    const float* w2i = (const float*)d_in[4];
    const float* w3r = (const float*)d_in[5];
    const float* w3i = (const float*)d_in[6];
    const float* w4r = (const float*)d_in[7];
    const float* w4i = (const float*)d_in[8];
    float* out = (float*)d_out;

    float *pBt, *pA2, *pA3, *pCmT2, *pT1R, *pT2, *pS2, *pY2R;
    cudaGetSymbolAddress((void**)&pBt,   g_Bt);
    cudaGetSymbolAddress((void**)&pA2,   g_A2);
    cudaGetSymbolAddress((void**)&pA3,   g_A3);
    cudaGetSymbolAddress((void**)&pCmT2, g_CmT2);
    cudaGetSymbolAddress((void**)&pT1R,  g_t1R);
    cudaGetSymbolAddress((void**)&pT2,   g_T2);
    cudaGetSymbolAddress((void**)&pS2,   g_S2);
    cudaGetSymbolAddress((void**)&pY2R,  g_Y2R);

    init_tables_k<<<64, 256>>>();

    // F1: t1R = Bt . x^T   (M=128, N=131072, K=256)
    gemm_tc<1, 1, 1><<<dim3(1, 1024), 256>>>(pBt, x, pT1R, 256, 0);

    // F2: T2 = A2 . t1R^T  (M=128, N=32768, K=512)
    gemm_tc<0, 0, 0><<<dim3(1, 256), 256>>>(pA2, pT1R, pT2, 512, 32768);

    // z-branch mode transpose
    tr_z_k<<<512, 256>>>();

    // channel mix (fp32), per-warp cp.async weight staging
    mix_k<<<dim3(64, 2), 512>>>(w1r, w1i, w2r, w2i, w3r, w3i, w4r, w4i);

    // S2T -> S2 row-major
    tr_s_k<<<dim3(512, 4, 2), dim3(32, 8)>>>();

    // I1: Y2R = A3 . S2^T  (M=512, N=16384, K=128), per branch
    gemm_tc<0, 1, 2><<<dim3(4, 128), 256>>>(pA3, pS2,               pY2R,                128, 0);
    gemm_tc<0, 1, 2><<<dim3(4, 128), 256>>>(pA3, pS2 + 16384 * 128, pY2R + 131072 * 64,  128, 0);

    // I2: out = Y2R . CmT2^T (M=131072, N=256, K=64), per branch
    gemm_tc<0, 0, 0><<<dim3(1024, 2), 256>>>(pY2R,               pCmT2, out,           64, 256);
    gemm_tc<0, 0, 0><<<dim3(1024, 2), 256>>>(pY2R + 131072 * 64, pCmT2, out + OUTOFF_, 64, 256);
}

// round 15
// speedup vs baseline: 1.7936x; 1.0526x over previous
#include <cuda_runtime.h>
#include <cstdint>

// ---------------------------------------------------------------------------
// SpectralConv2d (FNO) without FFT: whole pipeline as tf32 mma.sync GEMMs with
// dense (coalesced) operand layouts. Mix uses a 4-stage per-warp cp.async
// weight ring (wait_group 3); I1/I2 branch pairs merged via grid.z.
// (Identical to R12 submission — infra failure, never ran.)
// ---------------------------------------------------------------------------

namespace {
constexpr int ROWS_   = 131072;      // B*C*H
constexpr int OUTOFF_ = 33554432;    // B*COUT*H*W
constexpr int MIX_SMEM = (8 * 8 * 32 * 2 + 16 * 4 * 256) * 4;  // 16KB Ts + 64KB Wst
}

// ------------------------- static device scratch ---------------------------
__device__ __align__(16) float g_Bt  [128 * 256];
__device__ __align__(16) float g_A2  [128 * 512];
__device__ __align__(16) float g_A3  [512 * 128];
__device__ __align__(16) float g_CmT2[256 * 64];
__device__ __align__(16) float g_t1R [512 * 32768];      // 64MB
__device__ __align__(16) float g_T2  [128 * 32768];      // 16MB
__device__ __align__(16) float g_T2z [128 * 16384];      // 8MB
__device__ __align__(16) float g_S2T [2 * 128 * 16384];  // 16MB (plane-major)
__device__ __align__(16) float g_S2  [2 * 16384 * 128];  // 16MB (row-major, I1 B)
__device__ __align__(16) float g_Y2R [2 * 131072 * 64];  // 67MB

// ------------------------------ helpers ------------------------------------
__device__ __forceinline__ float to_tf32(float x) {
    float r; asm("cvt.rna.tf32.f32 %0, %1;" : "=f"(r) : "f"(x)); return r;
}
#define CP_ASYNC16(dst_u32, src_ptr) \
    asm volatile("cp.async.cg.shared.global [%0], [%1], 16;" :: "r"(dst_u32), "l"(src_ptr))
#define CP_COMMIT() asm volatile("cp.async.commit_group;")
#define CP_WAIT(n)  asm volatile("cp.async.wait_group %0;" :: "n"(n))
#define SADDR(p) ((uint32_t)__cvta_generic_to_shared(p))

#define MMA_TF32(d0,d1,d2,d3, a0,a1,a2,a3, b0,b1)                                   \
    asm volatile("mma.sync.aligned.m16n8k8.row.col.f32.tf32.tf32.f32 "              \
        "{%0,%1,%2,%3}, {%4,%5,%6,%7}, {%8,%9}, {%0,%1,%2,%3};"                     \
        : "+f"(d0), "+f"(d1), "+f"(d2), "+f"(d3)                                    \
        : "r"(a0), "r"(a1), "r"(a2), "r"(a3), "r"(b0), "r"(b1))

// ------------------------------ table init --------------------------------
__global__ void init_tables_k() {
    int t = blockIdx.x * blockDim.x + threadIdx.x;
    if (t >= 64 * 256) return;
    int m = t >> 8, n = t & 255;
    int mf = (m < 32) ? m : m + 192;
    int k = (mf * n) & 255;
    float s, c;
    sincospif((float)k * (1.0f / 128.0f), &s, &c);
    float tc = to_tf32(c), ts = to_tf32(s), tns = to_tf32(-s);

    g_Bt[(2 * m) * 256 + n]     = tc;
    g_Bt[(2 * m + 1) * 256 + n] = tns;
    g_A2[(2 * m) * 512 + n]           = tc;
    g_A2[(2 * m) * 512 + 256 + n]     = ts;
    g_A2[(2 * m + 1) * 512 + n]       = tns;
    g_A2[(2 * m + 1) * 512 + 256 + n] = tc;
    g_A3[(2 * n) * 128 + m]          = tc;
    g_A3[(2 * n) * 128 + 64 + m]     = tns;
    g_A3[(2 * n + 1) * 128 + m]      = ts;
    g_A3[(2 * n + 1) * 128 + 64 + m] = tc;

    int k2 = m & 31;
    int kk = (k2 * n) & 255;
    float s2, c2;
    sincospif((float)kk * (1.0f / 128.0f), &s2, &c2);
    const float sc = 1.0f / 65536.0f;
    float v;
    if (m < 32) v = (k2 == 0) ? sc : 2.0f * sc * c2;
    else        v = (k2 == 0) ? 0.0f : -2.0f * sc * s2;
    g_CmT2[n * 64 + m] = to_tf32(v);
}

// -------------------- tf32 mma.sync GEMM -----------------------------------
template<int EPI>
__device__ __forceinline__ void epi_store(float* C, size_t r0, size_t cb, int ldc,
                                          float v0, float v1) {
    size_t addr;
    if (EPI == 0)      addr = r0 * (size_t)ldc + cb;
    else if (EPI == 1) addr = (cb >> 8) * 32768 + (r0 >> 1) * 512 + (r0 & 1) * 256 + (cb & 255);
    else               addr = ((cb >> 5) * 256 + (r0 >> 1)) * 64 + (r0 & 1) * 32 + (cb & 31);
    *(float2*)&C[addr] = make_float2(v0, v1);
}

template<int CVTB, int CVTC, int EPI>
__global__ __launch_bounds__(256)
void gemm_tc(const float* __restrict__ A, const float* __restrict__ Bt,
             float* __restrict__ C, int K, int ldc,
             size_t zA, size_t zB, size_t zC) {
    A  += (size_t)blockIdx.z * zA;
    Bt += (size_t)blockIdx.z * zB;
    C  += (size_t)blockIdx.z * zC;
    __shared__ float As[2][128][20];
    __shared__ float Bs[2][128][20];
    int t = threadIdx.x;
    int warp = t >> 5, lane = t & 31;
    int gid = lane >> 2, tig = lane & 3;
    int wm = warp & 1, wn = warp >> 1;
    size_t m0 = (size_t)blockIdx.x * 128;
    size_t n0 = (size_t)blockIdx.y * 128;
    int nK = K >> 4;

    float acc[4][4][4];
#pragma unroll
    for (int mi = 0; mi < 4; mi++)
#pragma unroll
        for (int ni = 0; ni < 4; ni++)
#pragma unroll
            for (int r = 0; r < 4; r++) acc[mi][ni][r] = 0.0f;

    int lr  = t >> 2;
    int lc4 = (t & 3) * 4;

    auto load_stage = [&](int s, int k0) {
#pragma unroll
        for (int i = 0; i < 2; i++) {
            int r = i * 64 + lr;
            uint32_t da = (uint32_t)__cvta_generic_to_shared(&As[s][r][lc4]);
            CP_ASYNC16(da, &A[(m0 + r) * K + k0 + lc4]);
            uint32_t db = (uint32_t)__cvta_generic_to_shared(&Bs[s][r][lc4]);
            CP_ASYNC16(db, &Bt[(n0 + r) * K + k0 + lc4]);
        }
        CP_COMMIT();
    };

    load_stage(0, 0);
    for (int k0 = 0; k0 < nK; k0++) {
        int s = k0 & 1;
        if (k0 + 1 < nK) { load_stage(s ^ 1, (k0 + 1) << 4); CP_WAIT(1); }
        else             { CP_WAIT(0); }
        __syncthreads();
#pragma unroll
        for (int kk = 0; kk < 16; kk += 8) {
            uint32_t af[4][4], bf[4][2];
#pragma unroll
            for (int mi = 0; mi < 4; mi++) {
                int mr = wm * 64 + mi * 16 + gid;
                af[mi][0] = __float_as_uint(As[s][mr][kk + tig]);
                af[mi][1] = __float_as_uint(As[s][mr + 8][kk + tig]);
                af[mi][2] = __float_as_uint(As[s][mr][kk + tig + 4]);
                af[mi][3] = __float_as_uint(As[s][mr + 8][kk + tig + 4]);
            }
#pragma unroll
            for (int ni = 0; ni < 4; ni++) {
                int nr = wn * 32 + ni * 8 + gid;
                float b0 = Bs[s][nr][kk + tig], b1 = Bs[s][nr][kk + tig + 4];
                if (CVTB) { b0 = to_tf32(b0); b1 = to_tf32(b1); }
                bf[ni][0] = __float_as_uint(b0);
                bf[ni][1] = __float_as_uint(b1);
            }
#pragma unroll
            for (int mi = 0; mi < 4; mi++)
#pragma unroll
                for (int ni = 0; ni < 4; ni++)
                    MMA_TF32(acc[mi][ni][0], acc[mi][ni][1], acc[mi][ni][2], acc[mi][ni][3],
                             af[mi][0], af[mi][1], af[mi][2], af[mi][3],
                             bf[ni][0], bf[ni][1]);
        }
        __syncthreads();
    }

#pragma unroll
    for (int mi = 0; mi < 4; mi++) {
        size_t r0 = m0 + wm * 64 + mi * 16 + gid;
#pragma unroll
        for (int ni = 0; ni < 4; ni++) {
            size_t cb = n0 + wn * 32 + ni * 8 + tig * 2;
            float v0 = acc[mi][ni][0], v1 = acc[mi][ni][1];
            float v2 = acc[mi][ni][2], v3 = acc[mi][ni][3];
            if (CVTC) { v0 = to_tf32(v0); v1 = to_tf32(v1); v2 = to_tf32(v2); v3 = to_tf32(v3); }
            epi_store<EPI>(C, r0,     cb, ldc, v0, v1);
            epi_store<EPI>(C, r0 + 8, cb, ldc, v2, v3);
        }
    }
}

// ------------- T2 -> T2z: z-branch mode transpose (p<32, q<64) -------------
__global__ __launch_bounds__(256)
void tr_z_k() {
    __shared__ float tile[2][32][65];
    int bc = blockIdx.x;
    int t = threadIdx.x;
#pragma unroll
    for (int i = 0; i < 16; i++) {
        int lin = i * 256 + t;
        int e = lin >> 11, rem = lin & 2047;
        int p = rem >> 6, q = rem & 63;
        tile[e][p][q] = g_T2[(size_t)(2 * p + e) * 32768 + bc * 64 + q];
    }
    __syncthreads();
#pragma unroll
    for (int i = 0; i < 16; i++) {
        int lin = i * 256 + t;
        int e = lin >> 11, rem = lin & 2047;
        int q = rem >> 5, p = rem & 31;
        g_T2z[(size_t)(2 * q + e) * 16384 + bc * 32 + p] = tile[e][p][q];
    }
}

// ----------------- S2T (plane-major) -> S2 (row-major, I1 B) ---------------
__global__ void tr_s_k() {
    __shared__ float tile[32][33];
    int zb = blockIdx.z;
    int n0 = blockIdx.x * 32, p0 = blockIdx.y * 32;
    const float* src = g_S2T + (size_t)zb * 128 * 16384;
    float* dst = g_S2 + (size_t)zb * 16384 * 128;
    int tx = threadIdx.x, ty = threadIdx.y;
#pragma unroll
    for (int k = 0; k < 32; k += 8)
        tile[ty + k][tx] = src[(size_t)(p0 + ty + k) * 16384 + n0 + tx];
    __syncthreads();
#pragma unroll
    for (int k = 0; k < 32; k += 8)
        dst[(size_t)(n0 + ty + k) * 128 + p0 + tx] = tile[tx][ty + k];
}

// ---------------- channel mix (4-stage cp.async weight ring) ---------------
// grid (64 p, 2 branch); 16 warps, warp -> co = warp*4+j, lane -> k2.
__global__ __launch_bounds__(512)
void mix_k(const float* __restrict__ w1r, const float* __restrict__ w1i,
           const float* __restrict__ w2r, const float* __restrict__ w2i,
           const float* __restrict__ w3r, const float* __restrict__ w3i,
           const float* __restrict__ w4r, const float* __restrict__ w4i) {
    int p  = blockIdx.x;
    int zb = blockIdx.y;
    int pm = p & 31;
    const float *wr, *wi;
    if (!zb) { wr = (p < 32) ? w1r : w2r; wi = (p < 32) ? w1i : w2i; }
    else     { wr = (p < 32) ? w3r : w4r; wi = (p < 32) ? w3i : w4i; }
    float* Sout = g_S2T + (size_t)zb * 128 * 16384;

    int t = threadIdx.x;
    int lane = t & 31;
    int warp = t >> 5;
    extern __shared__ float smix[];
    float2* Ts  = (float2*)smix;           // [8 ci_l][8 b][32 q]  (16KB)
    float*  Wst = smix + 4096;             // [16 warp][4 st][256] (64KB)
    float* Wme = Wst + warp * 1024;

    float2 acc[8][4];
#pragma unroll
    for (int b = 0; b < 8; b++)
#pragma unroll
        for (int j = 0; j < 4; j++) acc[b][j] = make_float2(0.f, 0.f);

    int j_ld = lane >> 3;            // 0..3
    int l4   = (lane & 7) * 4;       // 0,4,...,28

    auto load_ts = [&](int cc) {
#pragma unroll
        for (int i = 0; i < 4; i++) {
            int lin = i * 512 + t;
            int ci_l = lin >> 8;
            int b = (lin >> 5) & 7;
            int q = lin & 31;
            int ci = cc + ci_l;
            float re, im;
            if (!zb) {
                size_t ix = (size_t)(2 * p) * 32768 + ((b * 64 + ci) * 64 + q);
                re = g_T2[ix]; im = g_T2[ix + 32768];
            } else {
                size_t ix = (size_t)(2 * p) * 16384 + ((b * 64 + ci) * 32 + q);
                re = g_T2z[ix]; im = g_T2z[ix + 16384];
            }
            Ts[(ci_l * 8 + b) * 32 + q] = make_float2(re, im);
        }
    };

    auto stage_w = [&](int st, int ci) {
        size_t off = ((size_t)(ci * 64 + warp * 4 + j_ld) * 32 + pm) * 32 + l4;
        CP_ASYNC16(SADDR(&Wme[st * 256 + j_ld * 32 + l4]), wr + off);
        CP_ASYNC16(SADDR(&Wme[st * 256 + 128 + j_ld * 32 + l4]), wi + off);
        CP_COMMIT();
    };

    load_ts(0);
    __syncthreads();
    stage_w(0, 0);
    stage_w(1, 1);
    stage_w(2, 2);

    for (int ci = 0; ci < 64; ci++) {
        int st = ci & 3;
        __syncwarp();                        // reads of the slot being reused done
        if (ci + 3 < 64) stage_w((ci + 3) & 3, ci + 3);
        if      (ci <= 60) CP_WAIT(3);
        else if (ci == 61) CP_WAIT(2);
        else if (ci == 62) CP_WAIT(1);
        else               CP_WAIT(0);
        __syncwarp();                        // stage st visible warp-wide

        float wr4[4], wi4[4];
#pragma unroll
        for (int j = 0; j < 4; j++) {
            wr4[j] = Wme[st * 256 + j * 32 + lane];
            wi4[j] = Wme[st * 256 + 128 + j * 32 + lane];
        }
        int ci_l = ci & 7;
#pragma unroll
        for (int b = 0; b < 8; b++) {
            float2 tv = Ts[(ci_l * 8 + b) * 32 + lane];
#pragma unroll
            for (int j = 0; j < 4; j++) {
                acc[b][j].x = fmaf(tv.x, wr4[j], fmaf(-tv.y, wi4[j], acc[b][j].x));
                acc[b][j].y = fmaf(tv.x, wi4[j], fmaf( tv.y, wr4[j], acc[b][j].y));
            }
        }
        if (ci_l == 7 && ci + 1 < 64) {
            __syncthreads();
            load_ts(ci + 1);
            __syncthreads();
        }
    }

#pragma unroll
    for (int b = 0; b < 8; b++)
#pragma unroll
        for (int j = 0; j < 4; j++) {
            int co = warp * 4 + j;
            size_t n = (size_t)(b * 64 + co) * 32 + lane;
            Sout[(size_t)p * 16384 + n]        = to_tf32(acc[b][j].x);
            Sout[(size_t)(64 + p) * 16384 + n] = to_tf32(acc[b][j].y);
        }
}

// ------------------------------- launcher ----------------------------------
extern "C" void kernel_launch(void* const* d_in, const int* in_sizes, int n_in,
                              void* d_out, int out_size) {
    const float* x   = (const float*)d_in[0];
    const float* w1r = (const float*)d_in[1];
    const float* w1i = (const float*)d_in[2];
    const float* w2r = (const float*)d_in[3];
    const float* w2i = (const float*)d_in[4];
    const float* w3r = (const float*)d_in[5];
    const float* w3i = (const float*)d_in[6];
    const float* w4r = (const float*)d_in[7];
    const float* w4i = (const float*)d_in[8];
    float* out = (float*)d_out;

    float *pBt, *pA2, *pA3, *pCmT2, *pT1R, *pT2, *pS2, *pY2R;
    cudaGetSymbolAddress((void**)&pBt,   g_Bt);
    cudaGetSymbolAddress((void**)&pA2,   g_A2);
    cudaGetSymbolAddress((void**)&pA3,   g_A3);
    cudaGetSymbolAddress((void**)&pCmT2, g_CmT2);
    cudaGetSymbolAddress((void**)&pT1R,  g_t1R);
    cudaGetSymbolAddress((void**)&pT2,   g_T2);
    cudaGetSymbolAddress((void**)&pS2,   g_S2);
    cudaGetSymbolAddress((void**)&pY2R,  g_Y2R);

    cudaFuncSetAttribute(mix_k, cudaFuncAttributeMaxDynamicSharedMemorySize, MIX_SMEM);

    init_tables_k<<<64, 256>>>();

    // F1: t1R = Bt . x^T   (M=128, N=131072, K=256)
    gemm_tc<1, 1, 1><<<dim3(1, 1024), 256>>>(pBt, x, pT1R, 256, 0, 0, 0, 0);

    // F2: T2 = A2 . t1R^T  (M=128, N=32768, K=512)
    gemm_tc<0, 0, 0><<<dim3(1, 256), 256>>>(pA2, pT1R, pT2, 512, 32768, 0, 0, 0);

    // z-branch mode transpose
    tr_z_k<<<512, 256>>>();

    // channel mix (fp32), 4-stage cp.async weight ring
    mix_k<<<dim3(64, 2), 512, MIX_SMEM>>>(w1r, w1i, w2r, w2i, w3r, w3i, w4r, w4i);

    // S2T -> S2 row-major
    tr_s_k<<<dim3(512, 4, 2), dim3(32, 8)>>>();

    // I1: Y2R = A3 . S2^T  (M=512, N=16384, K=128), branches via grid.z
    gemm_tc<0, 1, 2><<<dim3(4, 128, 2), 256>>>(pA3, pS2, pY2R, 128, 0,
                                               0, (size_t)16384 * 128, (size_t)131072 * 64);

    // I2: out = Y2R . CmT2^T (M=131072, N=256, K=64), branches via grid.z
    // N=256 -> grid.y=2 (two 128-col tiles); branches -> grid.z=2.
    gemm_tc<0, 0, 0><<<dim3(1024, 2, 2), 256>>>(pY2R, pCmT2, out, 64, 256,
                                                (size_t)131072 * 64, 0, (size_t)OUTOFF_);
}

// round 16
// speedup vs baseline: 1.8175x; 1.0133x over previous
#include <cuda_runtime.h>
#include <cstdint>

// ---------------------------------------------------------------------------
// SpectralConv2d (FNO) without FFT: whole pipeline as tf32 mma.sync GEMMs.
//   F1 : t1R = Bt . x^T                  (gemm_tc, EPI1 relayout)
//   f2z: T2 + T2z = A2 . t1R^T           (fused transpose epilogue)
//   mix: fp32 FFMA, 4-stage cp.async weight ring, writes S2T (tf32-rounded)
//   i1t: Y2R = A3 . S2T^T                (B staged transposed from S2T)
//   I2 : out = Y2R . CmT2^T              (gemm_tc, branches via grid.z)
// tr_z_k / tr_s_k / g_S2 eliminated.
// ---------------------------------------------------------------------------

namespace {
constexpr int ROWS_   = 131072;      // B*C*H
constexpr int OUTOFF_ = 33554432;    // B*COUT*H*W
constexpr int MIX_SMEM = (8 * 8 * 32 * 2 + 16 * 4 * 256) * 4;   // 16KB Ts + 64KB Wst
constexpr int F2Z_SMEM = (2 * 128 * 20 * 2 + 128 * 132) * 4;    // 40KB tiles + 67.6KB stage
}

// ------------------------- static device scratch ---------------------------
__device__ __align__(16) float g_Bt  [128 * 256];
__device__ __align__(16) float g_A2  [128 * 512];
__device__ __align__(16) float g_A3  [512 * 128];
__device__ __align__(16) float g_CmT2[256 * 64];
__device__ __align__(16) float g_t1R [512 * 32768];      // 64MB
__device__ __align__(16) float g_T2  [128 * 32768];      // 16MB
__device__ __align__(16) float g_T2z [128 * 16384];      // 8MB
__device__ __align__(16) float g_S2T [2 * 128 * 16384];  // 16MB (plane-major)
__device__ __align__(16) float g_Y2R [2 * 131072 * 64];  // 67MB

// ------------------------------ helpers ------------------------------------
__device__ __forceinline__ float to_tf32(float x) {
    float r; asm("cvt.rna.tf32.f32 %0, %1;" : "=f"(r) : "f"(x)); return r;
}
#define CP_ASYNC16(dst_u32, src_ptr) \
    asm volatile("cp.async.cg.shared.global [%0], [%1], 16;" :: "r"(dst_u32), "l"(src_ptr))
#define CP_COMMIT() asm volatile("cp.async.commit_group;")
#define CP_WAIT(n)  asm volatile("cp.async.wait_group %0;" :: "n"(n))
#define SADDR(p) ((uint32_t)__cvta_generic_to_shared(p))

#define MMA_TF32(d0,d1,d2,d3, a0,a1,a2,a3, b0,b1)                                   \
    asm volatile("mma.sync.aligned.m16n8k8.row.col.f32.tf32.tf32.f32 "              \
        "{%0,%1,%2,%3}, {%4,%5,%6,%7}, {%8,%9}, {%0,%1,%2,%3};"                     \
        : "+f"(d0), "+f"(d1), "+f"(d2), "+f"(d3)                                    \
        : "r"(a0), "r"(a1), "r"(a2), "r"(a3), "r"(b0), "r"(b1))

// ------------------------------ table init --------------------------------
__global__ void init_tables_k() {
    int t = blockIdx.x * blockDim.x + threadIdx.x;
    if (t >= 64 * 256) return;
    int m = t >> 8, n = t & 255;
    int mf = (m < 32) ? m : m + 192;
    int k = (mf * n) & 255;
    float s, c;
    sincospif((float)k * (1.0f / 128.0f), &s, &c);
    float tc = to_tf32(c), ts = to_tf32(s), tns = to_tf32(-s);

    g_Bt[(2 * m) * 256 + n]     = tc;
    g_Bt[(2 * m + 1) * 256 + n] = tns;
    g_A2[(2 * m) * 512 + n]           = tc;
    g_A2[(2 * m) * 512 + 256 + n]     = ts;
    g_A2[(2 * m + 1) * 512 + n]       = tns;
    g_A2[(2 * m + 1) * 512 + 256 + n] = tc;
    g_A3[(2 * n) * 128 + m]          = tc;
    g_A3[(2 * n) * 128 + 64 + m]     = tns;
    g_A3[(2 * n + 1) * 128 + m]      = ts;
    g_A3[(2 * n + 1) * 128 + 64 + m] = tc;

    int k2 = m & 31;
    int kk = (k2 * n) & 255;
    float s2, c2;
    sincospif((float)kk * (1.0f / 128.0f), &s2, &c2);
    const float sc = 1.0f / 65536.0f;
    float v;
    if (m < 32) v = (k2 == 0) ? sc : 2.0f * sc * c2;
    else        v = (k2 == 0) ? 0.0f : -2.0f * sc * s2;
    g_CmT2[n * 64 + m] = to_tf32(v);
}

// -------------------- tf32 mma.sync GEMM (F1, I2) --------------------------
template<int EPI>
__device__ __forceinline__ void epi_store(float* C, size_t r0, size_t cb, int ldc,
                                          float v0, float v1) {
    size_t addr;
    if (EPI == 0)      addr = r0 * (size_t)ldc + cb;
    else if (EPI == 1) addr = (cb >> 8) * 32768 + (r0 >> 1) * 512 + (r0 & 1) * 256 + (cb & 255);
    else               addr = ((cb >> 5) * 256 + (r0 >> 1)) * 64 + (r0 & 1) * 32 + (cb & 31);
    *(float2*)&C[addr] = make_float2(v0, v1);
}

template<int CVTB, int CVTC, int EPI>
__global__ __launch_bounds__(256)
void gemm_tc(const float* __restrict__ A, const float* __restrict__ Bt,
             float* __restrict__ C, int K, int ldc,
             size_t zA, size_t zB, size_t zC) {
    A  += (size_t)blockIdx.z * zA;
    Bt += (size_t)blockIdx.z * zB;
    C  += (size_t)blockIdx.z * zC;
    __shared__ float As[2][128][20];
    __shared__ float Bs[2][128][20];
    int t = threadIdx.x;
    int warp = t >> 5, lane = t & 31;
    int gid = lane >> 2, tig = lane & 3;
    int wm = warp & 1, wn = warp >> 1;
    size_t m0 = (size_t)blockIdx.x * 128;
    size_t n0 = (size_t)blockIdx.y * 128;
    int nK = K >> 4;

    float acc[4][4][4];
#pragma unroll
    for (int mi = 0; mi < 4; mi++)
#pragma unroll
        for (int ni = 0; ni < 4; ni++)
#pragma unroll
            for (int r = 0; r < 4; r++) acc[mi][ni][r] = 0.0f;

    int lr  = t >> 2;
    int lc4 = (t & 3) * 4;

    auto load_stage = [&](int s, int k0) {
#pragma unroll
        for (int i = 0; i < 2; i++) {
            int r = i * 64 + lr;
            CP_ASYNC16(SADDR(&As[s][r][lc4]), &A[(m0 + r) * K + k0 + lc4]);
            CP_ASYNC16(SADDR(&Bs[s][r][lc4]), &Bt[(n0 + r) * K + k0 + lc4]);
        }
        CP_COMMIT();
    };

    load_stage(0, 0);
    for (int k0 = 0; k0 < nK; k0++) {
        int s = k0 & 1;
        if (k0 + 1 < nK) { load_stage(s ^ 1, (k0 + 1) << 4); CP_WAIT(1); }
        else             { CP_WAIT(0); }
        __syncthreads();
#pragma unroll
        for (int kk = 0; kk < 16; kk += 8) {
            uint32_t af[4][4], bf[4][2];
#pragma unroll
            for (int mi = 0; mi < 4; mi++) {
                int mr = wm * 64 + mi * 16 + gid;
                af[mi][0] = __float_as_uint(As[s][mr][kk + tig]);
                af[mi][1] = __float_as_uint(As[s][mr + 8][kk + tig]);
                af[mi][2] = __float_as_uint(As[s][mr][kk + tig + 4]);
                af[mi][3] = __float_as_uint(As[s][mr + 8][kk + tig + 4]);
            }
#pragma unroll
            for (int ni = 0; ni < 4; ni++) {
                int nr = wn * 32 + ni * 8 + gid;
                float b0 = Bs[s][nr][kk + tig], b1 = Bs[s][nr][kk + tig + 4];
                if (CVTB) { b0 = to_tf32(b0); b1 = to_tf32(b1); }
                bf[ni][0] = __float_as_uint(b0);
                bf[ni][1] = __float_as_uint(b1);
            }
#pragma unroll
            for (int mi = 0; mi < 4; mi++)
#pragma unroll
                for (int ni = 0; ni < 4; ni++)
                    MMA_TF32(acc[mi][ni][0], acc[mi][ni][1], acc[mi][ni][2], acc[mi][ni][3],
                             af[mi][0], af[mi][1], af[mi][2], af[mi][3],
                             bf[ni][0], bf[ni][1]);
        }
        __syncthreads();
    }

#pragma unroll
    for (int mi = 0; mi < 4; mi++) {
        size_t r0 = m0 + wm * 64 + mi * 16 + gid;
#pragma unroll
        for (int ni = 0; ni < 4; ni++) {
            size_t cb = n0 + wn * 32 + ni * 8 + tig * 2;
            float v0 = acc[mi][ni][0], v1 = acc[mi][ni][1];
            float v2 = acc[mi][ni][2], v3 = acc[mi][ni][3];
            if (CVTC) { v0 = to_tf32(v0); v1 = to_tf32(v1); v2 = to_tf32(v2); v3 = to_tf32(v3); }
            epi_store<EPI>(C, r0,     cb, ldc, v0, v1);
            epi_store<EPI>(C, r0 + 8, cb, ldc, v2, v3);
        }
    }
}

// ------------- F2 with fused T2z epilogue (replaces F2 + tr_z) -------------
// M=128 (pe), N tile 128 (2 bc), K=512. Stage tile in smem, emit T2 and T2z.
__global__ __launch_bounds__(256)
void f2z_k() {
    extern __shared__ float fsm[];
    float* Asd   = fsm;                 // [2][128][20]
    float* Bsd   = fsm + 5120;          // [2][128][20]
    float* stage = fsm + 10240;         // [128][132], col-xor-swizzled
    int t = threadIdx.x;
    int warp = t >> 5, lane = t & 31;
    int gid = lane >> 2, tig = lane & 3;
    int wm = warp & 1, wn = warp >> 1;
    int n0 = blockIdx.x * 128;
    const int K = 512, nK = 32;

    float acc[4][4][4];
#pragma unroll
    for (int mi = 0; mi < 4; mi++)
#pragma unroll
        for (int ni = 0; ni < 4; ni++)
#pragma unroll
            for (int r = 0; r < 4; r++) acc[mi][ni][r] = 0.0f;

    int lr  = t >> 2;
    int lc4 = (t & 3) * 4;

    auto load_stage = [&](int s, int k0) {
#pragma unroll
        for (int i = 0; i < 2; i++) {
            int r = i * 64 + lr;
            CP_ASYNC16(SADDR(&Asd[(s * 128 + r) * 20 + lc4]), &g_A2[(size_t)r * K + k0 + lc4]);
            CP_ASYNC16(SADDR(&Bsd[(s * 128 + r) * 20 + lc4]),
                       &g_t1R[(size_t)(n0 + r) * K + k0 + lc4]);
        }
        CP_COMMIT();
    };

    load_stage(0, 0);
    for (int k0 = 0; k0 < nK; k0++) {
        int s = k0 & 1;
        if (k0 + 1 < nK) { load_stage(s ^ 1, (k0 + 1) << 4); CP_WAIT(1); }
        else             { CP_WAIT(0); }
        __syncthreads();
#pragma unroll
        for (int kk = 0; kk < 16; kk += 8) {
            uint32_t af[4][4], bf[4][2];
#pragma unroll
            for (int mi = 0; mi < 4; mi++) {
                int mr = wm * 64 + mi * 16 + gid;
                af[mi][0] = __float_as_uint(Asd[(s * 128 + mr) * 20 + kk + tig]);
                af[mi][1] = __float_as_uint(Asd[(s * 128 + mr + 8) * 20 + kk + tig]);
                af[mi][2] = __float_as_uint(Asd[(s * 128 + mr) * 20 + kk + tig + 4]);
                af[mi][3] = __float_as_uint(Asd[(s * 128 + mr + 8) * 20 + kk + tig + 4]);
            }
#pragma unroll
            for (int ni = 0; ni < 4; ni++) {
                int nr = wn * 32 + ni * 8 + gid;
                bf[ni][0] = __float_as_uint(Bsd[(s * 128 + nr) * 20 + kk + tig]);
                bf[ni][1] = __float_as_uint(Bsd[(s * 128 + nr) * 20 + kk + tig + 4]);
            }
#pragma unroll
            for (int mi = 0; mi < 4; mi++)
#pragma unroll
                for (int ni = 0; ni < 4; ni++)
                    MMA_TF32(acc[mi][ni][0], acc[mi][ni][1], acc[mi][ni][2], acc[mi][ni][3],
                             af[mi][0], af[mi][1], af[mi][2], af[mi][3],
                             bf[ni][0], bf[ni][1]);
        }
        __syncthreads();
    }

    // stage tile: stage[r][c ^ swz(r)], swz(r) = ((r>>1)&7)<<2  (keeps 4-groups)
#pragma unroll
    for (int mi = 0; mi < 4; mi++) {
        int r0 = wm * 64 + mi * 16 + gid;
#pragma unroll
        for (int ni = 0; ni < 4; ni++) {
            int cb = wn * 32 + ni * 8 + tig * 2;
            int kA = ((r0 >> 1) & 7) << 2;
            int kB = (((r0 + 8) >> 1) & 7) << 2;
            *(float2*)&stage[r0 * 132 + (cb ^ kA)] =
                make_float2(acc[mi][ni][0], acc[mi][ni][1]);
            *(float2*)&stage[(r0 + 8) * 132 + (cb ^ kB)] =
                make_float2(acc[mi][ni][2], acc[mi][ni][3]);
        }
    }
    __syncthreads();

    // T2 writes: row-contiguous float4
#pragma unroll
    for (int i = 0; i < 16; i++) {
        int lin = i * 256 + t;
        int r = lin >> 5, c4 = (lin & 31) * 4;
        int k = ((r >> 1) & 7) << 2;
        float4 v = *(float4*)&stage[r * 132 + (c4 ^ k)];
        *(float4*)&g_T2[(size_t)r * 32768 + n0 + c4] = v;
    }
    // T2z writes: T2z[(2q+e)*16384 + bc*32 + p] = stage[2p+e][bcl*64+q], p<32
#pragma unroll
    for (int i = 0; i < 32; i++) {
        int lin = i * 256 + t;
        int p = lin & 31;
        int seg = lin >> 5;          // 0..255
        int bcl = seg & 1;
        int q = (seg >> 1) & 63;
        int e = seg >> 7;
        int lr2 = 2 * p + e;
        int lc = bcl * 64 + q;
        int k = ((lr2 >> 1) & 7) << 2;
        float v = stage[lr2 * 132 + (lc ^ k)];
        g_T2z[(size_t)(2 * q + e) * 16384 + (blockIdx.x * 2 + bcl) * 32 + p] = v;
    }
}

// ---------------- channel mix (4-stage cp.async weight ring) ---------------
__global__ __launch_bounds__(512)
void mix_k(const float* __restrict__ w1r, const float* __restrict__ w1i,
           const float* __restrict__ w2r, const float* __restrict__ w2i,
           const float* __restrict__ w3r, const float* __restrict__ w3i,
           const float* __restrict__ w4r, const float* __restrict__ w4i) {
    int p  = blockIdx.x;
    int zb = blockIdx.y;
    int pm = p & 31;
    const float *wr, *wi;
    if (!zb) { wr = (p < 32) ? w1r : w2r; wi = (p < 32) ? w1i : w2i; }
    else     { wr = (p < 32) ? w3r : w4r; wi = (p < 32) ? w3i : w4i; }
    float* Sout = g_S2T + (size_t)zb * 128 * 16384;

    int t = threadIdx.x;
    int lane = t & 31;
    int warp = t >> 5;
    extern __shared__ float smix[];
    float2* Ts  = (float2*)smix;           // [8 ci_l][8 b][32 q]  (16KB)
    float*  Wst = smix + 4096;             // [16 warp][4 st][256] (64KB)
    float* Wme = Wst + warp * 1024;

    float2 acc[8][4];
#pragma unroll
    for (int b = 0; b < 8; b++)
#pragma unroll
        for (int j = 0; j < 4; j++) acc[b][j] = make_float2(0.f, 0.f);

    int j_ld = lane >> 3;
    int l4   = (lane & 7) * 4;

    auto load_ts = [&](int cc) {
#pragma unroll
        for (int i = 0; i < 4; i++) {
            int lin = i * 512 + t;
            int ci_l = lin >> 8;
            int b = (lin >> 5) & 7;
            int q = lin & 31;
            int ci = cc + ci_l;
            float re, im;
            if (!zb) {
                size_t ix = (size_t)(2 * p) * 32768 + ((b * 64 + ci) * 64 + q);
                re = g_T2[ix]; im = g_T2[ix + 32768];
            } else {
                size_t ix = (size_t)(2 * p) * 16384 + ((b * 64 + ci) * 32 + q);
                re = g_T2z[ix]; im = g_T2z[ix + 16384];
            }
            Ts[(ci_l * 8 + b) * 32 + q] = make_float2(re, im);
        }
    };

    auto stage_w = [&](int st, int ci) {
        size_t off = ((size_t)(ci * 64 + warp * 4 + j_ld) * 32 + pm) * 32 + l4;
        CP_ASYNC16(SADDR(&Wme[st * 256 + j_ld * 32 + l4]), wr + off);
        CP_ASYNC16(SADDR(&Wme[st * 256 + 128 + j_ld * 32 + l4]), wi + off);
        CP_COMMIT();
    };

    load_ts(0);
    __syncthreads();
    stage_w(0, 0);
    stage_w(1, 1);
    stage_w(2, 2);

    for (int ci = 0; ci < 64; ci++) {
        int st = ci & 3;
        __syncwarp();
        if (ci + 3 < 64) stage_w((ci + 3) & 3, ci + 3);
        if      (ci <= 60) CP_WAIT(3);
        else if (ci == 61) CP_WAIT(2);
        else if (ci == 62) CP_WAIT(1);
        else               CP_WAIT(0);
        __syncwarp();

        float wr4[4], wi4[4];
#pragma unroll
        for (int j = 0; j < 4; j++) {
            wr4[j] = Wme[st * 256 + j * 32 + lane];
            wi4[j] = Wme[st * 256 + 128 + j * 32 + lane];
        }
        int ci_l = ci & 7;
#pragma unroll
        for (int b = 0; b < 8; b++) {
            float2 tv = Ts[(ci_l * 8 + b) * 32 + lane];
#pragma unroll
            for (int j = 0; j < 4; j++) {
                acc[b][j].x = fmaf(tv.x, wr4[j], fmaf(-tv.y, wi4[j], acc[b][j].x));
                acc[b][j].y = fmaf(tv.x, wi4[j], fmaf( tv.y, wr4[j], acc[b][j].y));
            }
        }
        if (ci_l == 7 && ci + 1 < 64) {
            __syncthreads();
            load_ts(ci + 1);
            __syncthreads();
        }
    }

#pragma unroll
    for (int b = 0; b < 8; b++)
#pragma unroll
        for (int j = 0; j < 4; j++) {
            int co = warp * 4 + j;
            size_t n = (size_t)(b * 64 + co) * 32 + lane;
            Sout[(size_t)p * 16384 + n]        = to_tf32(acc[b][j].x);
            Sout[(size_t)(64 + p) * 16384 + n] = to_tf32(acc[b][j].y);
        }
}

// ---------- I1 reading S2T directly (transposed B staging; no tr_s) --------
// Y2R[...] = A3(512x128) . S2T^T ; B rows of S2T are contiguous in n.
__global__ __launch_bounds__(256)
void i1t_k() {
    __shared__ float As[2][128][20];
    __shared__ float BsT[2][16][132];
    int t = threadIdx.x;
    int warp = t >> 5, lane = t & 31;
    int gid = lane >> 2, tig = lane & 3;
    int wm = warp & 1, wn = warp >> 1;
    size_t m0 = (size_t)blockIdx.x * 128;
    size_t n0 = (size_t)blockIdx.y * 128;
    const float* Sb = g_S2T + (size_t)blockIdx.z * 128 * 16384;
    float* Yout = g_Y2R + (size_t)blockIdx.z * 131072 * 64;
    const int nK = 8;   // K = 128

    float acc[4][4][4];
#pragma unroll
    for (int mi = 0; mi < 4; mi++)
#pragma unroll
        for (int ni = 0; ni < 4; ni++)
#pragma unroll
            for (int r = 0; r < 4; r++) acc[mi][ni][r] = 0.0f;

    int lr  = t >> 2;
    int lc4 = (t & 3) * 4;

    auto load_stage = [&](int s, int k0) {
#pragma unroll
        for (int i = 0; i < 2; i++) {
            int r = i * 64 + lr;
            CP_ASYNC16(SADDR(&As[s][r][lc4]), &g_A3[(m0 + r) * 128 + k0 + lc4]);
            int lin = i * 256 + t;                 // 512 float4 = 16 rows x 128
            int kr = lin >> 5, c4 = (lin & 31) * 4;
            CP_ASYNC16(SADDR(&BsT[s][kr][c4]), &Sb[(size_t)(k0 + kr) * 16384 + n0 + c4]);
        }
        CP_COMMIT();
    };

    load_stage(0, 0);
    for (int k0 = 0; k0 < nK; k0++) {
        int s = k0 & 1;
        if (k0 + 1 < nK) { load_stage(s ^ 1, (k0 + 1) << 4); CP_WAIT(1); }
        else             { CP_WAIT(0); }
        __syncthreads();
#pragma unroll
        for (int kk = 0; kk < 16; kk += 8) {
            uint32_t af[4][4], bf[4][2];
#pragma unroll
            for (int mi = 0; mi < 4; mi++) {
                int mr = wm * 64 + mi * 16 + gid;
                af[mi][0] = __float_as_uint(As[s][mr][kk + tig]);
                af[mi][1] = __float_as_uint(As[s][mr + 8][kk + tig]);
                af[mi][2] = __float_as_uint(As[s][mr][kk + tig + 4]);
                af[mi][3] = __float_as_uint(As[s][mr + 8][kk + tig + 4]);
            }
#pragma unroll
            for (int ni = 0; ni < 4; ni++) {
                int nr = wn * 32 + ni * 8 + gid;
                bf[ni][0] = __float_as_uint(BsT[s][kk + tig][nr]);
                bf[ni][1] = __float_as_uint(BsT[s][kk + tig + 4][nr]);
            }
#pragma unroll
            for (int mi = 0; mi < 4; mi++)
#pragma unroll
                for (int ni = 0; ni < 4; ni++)
                    MMA_TF32(acc[mi][ni][0], acc[mi][ni][1], acc[mi][ni][2], acc[mi][ni][3],
                             af[mi][0], af[mi][1], af[mi][2], af[mi][3],
                             bf[ni][0], bf[ni][1]);
        }
        __syncthreads();
    }

    // EPI2 relayout to Y2R (tf32-rounded)
#pragma unroll
    for (int mi = 0; mi < 4; mi++) {
        size_t r0 = m0 + wm * 64 + mi * 16 + gid;
#pragma unroll
        for (int ni = 0; ni < 4; ni++) {
            size_t cb = n0 + wn * 32 + ni * 8 + tig * 2;
            float v0 = to_tf32(acc[mi][ni][0]), v1 = to_tf32(acc[mi][ni][1]);
            float v2 = to_tf32(acc[mi][ni][2]), v3 = to_tf32(acc[mi][ni][3]);
            size_t a0 = ((cb >> 5) * 256 + (r0 >> 1)) * 64 + (r0 & 1) * 32 + (cb & 31);
            size_t a1 = ((cb >> 5) * 256 + ((r0 + 8) >> 1)) * 64 + ((r0 + 8) & 1) * 32 + (cb & 31);
            *(float2*)&Yout[a0] = make_float2(v0, v1);
            *(float2*)&Yout[a1] = make_float2(v2, v3);
        }
    }
}

// ------------------------------- launcher ----------------------------------
extern "C" void kernel_launch(void* const* d_in, const int* in_sizes, int n_in,
                              void* d_out, int out_size) {
    const float* x   = (const float*)d_in[0];
    const float* w1r = (const float*)d_in[1];
    const float* w1i = (const float*)d_in[2];
    const float* w2r = (const float*)d_in[3];
    const float* w2i = (const float*)d_in[4];
    const float* w3r = (const float*)d_in[5];
    const float* w3i = (const float*)d_in[6];
    const float* w4r = (const float*)d_in[7];
    const float* w4i = (const float*)d_in[8];
    float* out = (float*)d_out;

    float *pBt, *pCmT2, *pT1R, *pY2R;
    cudaGetSymbolAddress((void**)&pBt,   g_Bt);
    cudaGetSymbolAddress((void**)&pCmT2, g_CmT2);
    cudaGetSymbolAddress((void**)&pT1R,  g_t1R);
    cudaGetSymbolAddress((void**)&pY2R,  g_Y2R);

    cudaFuncSetAttribute(mix_k, cudaFuncAttributeMaxDynamicSharedMemorySize, MIX_SMEM);
    cudaFuncSetAttribute(f2z_k, cudaFuncAttributeMaxDynamicSharedMemorySize, F2Z_SMEM);

    init_tables_k<<<64, 256>>>();

    // F1: t1R = Bt . x^T   (M=128, N=131072, K=256)
    gemm_tc<1, 1, 1><<<dim3(1, 1024), 256>>>(pBt, x, pT1R, 256, 0, 0, 0, 0);

    // F2 + T2z fused epilogue
    f2z_k<<<256, 256, F2Z_SMEM>>>();

    // channel mix (fp32), 4-stage cp.async weight ring
    mix_k<<<dim3(64, 2), 512, MIX_SMEM>>>(w1r, w1i, w2r, w2i, w3r, w3i, w4r, w4i);

    // I1: Y2R = A3 . S2T^T  (M=512, N=16384, K=128), branches via grid.z
    i1t_k<<<dim3(4, 128, 2), 256>>>();

    // I2: out = Y2R . CmT2^T (M=131072, N=256, K=64), branches via grid.z
    gemm_tc<0, 0, 0><<<dim3(1024, 2, 2), 256>>>(pY2R, pCmT2, out, 64, 256,
                                                (size_t)131072 * 64, 0, (size_t)OUTOFF_);
}